// round 1
// baseline (speedup 1.0000x reference)
#include <cuda_runtime.h>
#include <math.h>

// Problem constants
#define BB   2
#define SS   2048
#define EE   2048
#define HH   16
#define KVH  4
#define DD   128
#define WINW 512
#define QKVW ((HH + 2*KVH) * DD)   // 3072
#define NROWS (BB * SS)            // 4096

// Scratch (static device globals — allocation-free per harness rules)
__device__ float g_qkv[(size_t)NROWS * QKVW];       // 4096 x 3072
__device__ float g_attn[(size_t)NROWS * HH * DD];   // 4096 x 2048

// ---------------------------------------------------------------------------
// SGEMM: C[M,N] = A[M,K] * B[K,N], fp32, BM=BN=128, BK=16, 256 thr, 8x8/thread
// Requires M%128==0, N%128==0, K%16==0 (true for all our shapes).
// ---------------------------------------------------------------------------
__global__ void __launch_bounds__(256) sgemm_kernel(
    const float* __restrict__ A, const float* __restrict__ B,
    float* __restrict__ C, int M, int N, int K)
{
    __shared__ float As[16][128];
    __shared__ float Bs[16][128];

    const int tid = threadIdx.x;
    const int tx  = tid & 15;        // 0..15 (n dir)
    const int ty  = tid >> 4;        // 0..15 (m dir)
    const int bm  = blockIdx.y * 128;
    const int bn  = blockIdx.x * 128;

    // A tile loader: row = tid/4 (+64), col4 = (tid%4)*4
    const int a_row = tid >> 2;
    const int a_col = (tid & 3) << 2;
    // B tile loader: row = tid/32 (+8), col4 = (tid%32)*4
    const int b_row = tid >> 5;
    const int b_col = (tid & 31) << 2;

    float acc[8][8];
    #pragma unroll
    for (int i = 0; i < 8; i++)
        #pragma unroll
        for (int j = 0; j < 8; j++) acc[i][j] = 0.f;

    for (int k0 = 0; k0 < K; k0 += 16) {
        #pragma unroll
        for (int r = 0; r < 2; r++) {
            int m = a_row + r * 64;
            float4 v = *(const float4*)&A[(size_t)(bm + m) * K + k0 + a_col];
            As[a_col + 0][m] = v.x;
            As[a_col + 1][m] = v.y;
            As[a_col + 2][m] = v.z;
            As[a_col + 3][m] = v.w;
        }
        #pragma unroll
        for (int r = 0; r < 2; r++) {
            int kk = b_row + r * 8;
            *(float4*)&Bs[kk][b_col] =
                *(const float4*)&B[(size_t)(k0 + kk) * N + bn + b_col];
        }
        __syncthreads();

        #pragma unroll
        for (int k = 0; k < 16; k++) {
            float ra[8], rb[8];
            #pragma unroll
            for (int i = 0; i < 4; i++) {
                float4 v = *(const float4*)&As[k][ty * 8 + i * 4];
                ra[i*4+0]=v.x; ra[i*4+1]=v.y; ra[i*4+2]=v.z; ra[i*4+3]=v.w;
            }
            #pragma unroll
            for (int i = 0; i < 4; i++) {
                float4 v = *(const float4*)&Bs[k][tx * 8 + i * 4];
                rb[i*4+0]=v.x; rb[i*4+1]=v.y; rb[i*4+2]=v.z; rb[i*4+3]=v.w;
            }
            #pragma unroll
            for (int i = 0; i < 8; i++)
                #pragma unroll
                for (int j = 0; j < 8; j++)
                    acc[i][j] += ra[i] * rb[j];
        }
        __syncthreads();
    }

    #pragma unroll
    for (int i = 0; i < 8; i++) {
        size_t row = (size_t)(bm + ty * 8 + i) * N + bn + tx * 8;
        *(float4*)&C[row + 0] = make_float4(acc[i][0], acc[i][1], acc[i][2], acc[i][3]);
        *(float4*)&C[row + 4] = make_float4(acc[i][4], acc[i][5], acc[i][6], acc[i][7]);
    }
}

// ---------------------------------------------------------------------------
// RoPE in-place on q (heads 0..15) and k (heads 16..19) slices of g_qkv.
// grid: (NROWS, HH+KVH), block: 64 threads (pair d, d+64).
// ---------------------------------------------------------------------------
__global__ void rope_kernel(float* __restrict__ qkv)
{
    const int bs   = blockIdx.x;            // 0..4095
    const int head = blockIdx.y;            // 0..19
    const int d    = threadIdx.x;           // 0..63
    const int s    = bs & (SS - 1);

    float* base = qkv + (size_t)bs * QKVW +
                  (head < HH ? head * DD : HH * DD + (head - HH) * DD);

    // inv_freq = theta^(-d/64), theta = 1e6 -> exp2(-d * log2(1e6)/64)
    const float inv_freq = exp2f(-(float)d * 0.311430758895690262f);
    const float ang = (float)s * inv_freq;
    float sn, cs;
    sincosf(ang, &sn, &cs);

    const float x0 = base[d];
    const float x1 = base[d + 64];
    base[d]      = x0 * cs - x1 * sn;
    base[d + 64] = x1 * cs + x0 * sn;
}

// ---------------------------------------------------------------------------
// Windowed causal GQA attention. One CTA per (b, h, 32-query tile).
// Full score strip for the tile (32 x <=544) lives in smem: exact softmax.
// ---------------------------------------------------------------------------
#define BQ 32
#define SKSTRIDE 545   // max keys 544, +1 pad

__global__ void __launch_bounds__(256) attn_kernel(
    const float* __restrict__ qkv, float* __restrict__ out)
{
    extern __shared__ float sm[];
    float* Qs  = sm;                       // [32][132]
    float* KVs = Qs + 32 * 132;            // [32][132]
    float* Sc  = KVs + 32 * 132;           // [32][545]

    const int tid = threadIdx.x;
    const int b   = blockIdx.z;
    const int h   = blockIdx.y;
    const int q0  = blockIdx.x * BQ;
    const int g   = h >> 2;                // kv head = h / (H/KV)
    const float scale = 0.088388347648318447f;  // 1/sqrt(128)

    // Load Q tile (pre-scaled)
    for (int idx = tid; idx < BQ * DD; idx += 256) {
        int qi = idx >> 7, d = idx & 127;
        Qs[qi * 132 + d] =
            qkv[((size_t)(b * SS + q0 + qi)) * QKVW + h * DD + d] * scale;
    }

    const int js = max(0, q0 - WINW);      // multiple of 32
    const int nk = q0 + BQ - js;           // <= 544
    __syncthreads();

    // ---- score phase: 32x32 tiles, thread computes 2q x 2k ----
    const int tq = (tid >> 4) << 1;        // 0,2,..,30
    const int tk = (tid & 15) << 1;        // 0,2,..,30
    for (int kt = 0; kt < nk; kt += 32) {
        for (int idx = tid; idx < 32 * DD; idx += 256) {
            int kj = idx >> 7, d = idx & 127;
            KVs[kj * 132 + d] =
                qkv[((size_t)(b * SS + js + kt + kj)) * QKVW + HH * DD + g * DD + d];
        }
        __syncthreads();

        float a00 = 0.f, a01 = 0.f, a10 = 0.f, a11 = 0.f;
        #pragma unroll 8
        for (int d = 0; d < DD; d++) {
            float qa = Qs[tq * 132 + d];
            float qb = Qs[(tq + 1) * 132 + d];
            float ka = KVs[tk * 132 + d];
            float kb = KVs[(tk + 1) * 132 + d];
            a00 += qa * ka; a01 += qa * kb;
            a10 += qb * ka; a11 += qb * kb;
        }
        const int i0 = q0 + tq, i1 = i0 + 1;
        const int j0 = js + kt + tk, j1 = j0 + 1;
        Sc[tq * SKSTRIDE + kt + tk]           = (j0 <= i0 && i0 - j0 < WINW) ? a00 : -1e30f;
        Sc[tq * SKSTRIDE + kt + tk + 1]       = (j1 <= i0 && i0 - j1 < WINW) ? a01 : -1e30f;
        Sc[(tq + 1) * SKSTRIDE + kt + tk]     = (j0 <= i1 && i1 - j0 < WINW) ? a10 : -1e30f;
        Sc[(tq + 1) * SKSTRIDE + kt + tk + 1] = (j1 <= i1 && i1 - j1 < WINW) ? a11 : -1e30f;
        __syncthreads();
    }

    // ---- softmax: 8 warps, 4 rows each ----
    const int warp = tid >> 5, lane = tid & 31;
    for (int row = warp; row < BQ; row += 8) {
        float m = -1e30f;
        for (int j = lane; j < nk; j += 32) m = fmaxf(m, Sc[row * SKSTRIDE + j]);
        #pragma unroll
        for (int o = 16; o; o >>= 1) m = fmaxf(m, __shfl_xor_sync(0xffffffffu, m, o));
        float ssum = 0.f;
        for (int j = lane; j < nk; j += 32) {
            float e = __expf(Sc[row * SKSTRIDE + j] - m);
            Sc[row * SKSTRIDE + j] = e;
            ssum += e;
        }
        #pragma unroll
        for (int o = 16; o; o >>= 1) ssum += __shfl_xor_sync(0xffffffffu, ssum, o);
        float inv = 1.0f / ssum;
        for (int j = lane; j < nk; j += 32) Sc[row * SKSTRIDE + j] *= inv;
    }
    __syncthreads();

    // ---- PV phase: thread owns 2 query rows x 8 d-cols ----
    const int qi0 = (tid & 15) << 1;       // 0..30
    const int dc  = (tid >> 4) << 3;       // 0..120
    float acc[2][8];
    #pragma unroll
    for (int r = 0; r < 2; r++)
        #pragma unroll
        for (int j = 0; j < 8; j++) acc[r][j] = 0.f;

    for (int kt = 0; kt < nk; kt += 32) {
        for (int idx = tid; idx < 32 * DD; idx += 256) {
            int kj = idx >> 7, d = idx & 127;
            KVs[kj * 132 + d] =
                qkv[((size_t)(b * SS + js + kt + kj)) * QKVW + (HH + KVH) * DD + g * DD + d];
        }
        __syncthreads();
        #pragma unroll 4
        for (int kj = 0; kj < 32; kj++) {
            float p0 = Sc[qi0 * SKSTRIDE + kt + kj];
            float p1 = Sc[(qi0 + 1) * SKSTRIDE + kt + kj];
            #pragma unroll
            for (int j = 0; j < 8; j++) {
                float v = KVs[kj * 132 + dc + j];
                acc[0][j] += p0 * v;
                acc[1][j] += p1 * v;
            }
        }
        __syncthreads();
    }

    #pragma unroll
    for (int r = 0; r < 2; r++) {
        float* dst = out + ((size_t)(b * SS + q0 + qi0 + r)) * (HH * DD) + h * DD + dc;
        #pragma unroll
        for (int j = 0; j < 8; j++) dst[j] = acc[r][j];
    }
}

// ---------------------------------------------------------------------------
extern "C" void kernel_launch(void* const* d_in, const int* in_sizes, int n_in,
                              void* d_out, int out_size)
{
    const float* x     = (const float*)d_in[0];   // [2,2048,2048]
    const float* w_qkv = (const float*)d_in[1];   // [2048,3072]
    const float* w_o   = (const float*)d_in[2];   // [2048,2048]
    float* out = (float*)d_out;                    // [2,2048,2048]

    float* qkv_ptr  = nullptr;
    float* attn_ptr = nullptr;
    cudaGetSymbolAddress((void**)&qkv_ptr,  g_qkv);
    cudaGetSymbolAddress((void**)&attn_ptr, g_attn);

    const int ATTN_SMEM = (32 * 132 + 32 * 132 + 32 * SKSTRIDE) * (int)sizeof(float);
    cudaFuncSetAttribute(attn_kernel,
                         cudaFuncAttributeMaxDynamicSharedMemorySize, ATTN_SMEM);

    // 1) QKV projection: [4096,2048] @ [2048,3072]
    {
        dim3 grid(QKVW / 128, NROWS / 128);
        sgemm_kernel<<<grid, 256>>>(x, w_qkv, qkv_ptr, NROWS, QKVW, EE);
    }
    // 2) RoPE in-place on q,k
    {
        dim3 grid(NROWS, HH + KVH);
        rope_kernel<<<grid, 64>>>(qkv_ptr);
    }
    // 3) Windowed GQA attention
    {
        dim3 grid(SS / BQ, HH, BB);
        attn_kernel<<<grid, 256, ATTN_SMEM>>>(qkv_ptr, attn_ptr);
    }
    // 4) Output projection: [4096,2048] @ [2048,2048]
    {
        dim3 grid(EE / 128, NROWS / 128);
        sgemm_kernel<<<grid, 256>>>(attn_ptr, w_o, out, NROWS, EE, EE);
    }
}

// round 2
// speedup vs baseline: 1.7633x; 1.7633x over previous
#include <cuda_runtime.h>
#include <math.h>
#include <stdint.h>

// Problem constants
#define BB   2
#define SS   2048
#define EE   2048
#define HH   16
#define KVH  4
#define DD   128
#define WINW 512
#define QKVW ((HH + 2*KVH) * DD)   // 3072
#define NROWS (BB * SS)            // 4096

// Scratch (static device globals — allocation-free per harness rules)
__device__ float g_qkv[(size_t)NROWS * QKVW];       // 4096 x 3072
__device__ float g_attn[(size_t)NROWS * HH * DD];   // 4096 x 2048

// ---------------------------------------------------------------------------
// TF32 tensor-core GEMM: C[M,N] = A[M,K] * B[K,N]
// BM=128, BN=128, BK=32, 256 threads, 8 warps (4x2), warp tile 32x64.
// mma.sync.aligned.m16n8k8.row.col.f32.tf32.tf32.f32
// Inputs converted to tf32 with round-to-nearest at staging time.
// Requires M%128==0, N%128==0, K%32==0.
// ---------------------------------------------------------------------------
#define GBK 32
#define ASTR 36    // As[m][k] stride (BK+4): frag bank = 4g+l4, conflict-free
#define BSTR 136   // Bs[k][n] stride (BN+8): frag bank = 8*l4+g, conflict-free
#define ASZ (128 * ASTR)
#define BSZ (GBK * BSTR)

__device__ __forceinline__ uint32_t f2tf(float x) {
    uint32_t r;
    asm volatile("cvt.rna.tf32.f32 %0, %1;" : "=r"(r) : "f"(x));
    return r;
}

__device__ __forceinline__ void mma_tf32(float* c, const uint32_t* a, const uint32_t* b) {
    asm volatile(
        "mma.sync.aligned.m16n8k8.row.col.f32.tf32.tf32.f32 "
        "{%0,%1,%2,%3}, {%4,%5,%6,%7}, {%8,%9}, {%0,%1,%2,%3};\n"
        : "+f"(c[0]), "+f"(c[1]), "+f"(c[2]), "+f"(c[3])
        : "r"(a[0]), "r"(a[1]), "r"(a[2]), "r"(a[3]), "r"(b[0]), "r"(b[1]));
}

__global__ void __launch_bounds__(256) gemm_tf32_kernel(
    const float* __restrict__ A, const float* __restrict__ B,
    float* __restrict__ C, int M, int N, int K)
{
    extern __shared__ uint32_t smu[];
    uint32_t* As = smu;              // [2][128][ASTR]
    uint32_t* Bs = smu + 2 * ASZ;    // [2][GBK][BSTR]

    const int tid    = threadIdx.x;
    const int warp   = tid >> 5;
    const int lane   = tid & 31;
    const int g      = lane >> 2;    // 0..7
    const int l4     = lane & 3;     // 0..3
    const int warp_m = warp >> 1;    // 0..3
    const int warp_n = warp & 1;     // 0..1
    const int bm     = blockIdx.y * 128;
    const int bn     = blockIdx.x * 128;

    // A loader: thread covers (a_m + p*32, a_k..a_k+3), p=0..3
    const int a_m = tid >> 3;
    const int a_k = (tid & 7) << 2;
    // B loader: thread covers (b_k + p*8, b_n..b_n+3), p=0..3
    const int b_k = tid >> 5;
    const int b_n = (tid & 31) << 2;

    float acc[2][8][4];
    #pragma unroll
    for (int mt = 0; mt < 2; mt++)
        #pragma unroll
        for (int nt = 0; nt < 8; nt++)
            #pragma unroll
            for (int i = 0; i < 4; i++) acc[mt][nt][i] = 0.f;

    const int nkt = K / GBK;

    float4 va[4], vb[4];

    // prologue: load + stage k-tile 0
    #pragma unroll
    for (int p = 0; p < 4; p++)
        va[p] = *(const float4*)&A[(size_t)(bm + a_m + p * 32) * K + a_k];
    #pragma unroll
    for (int p = 0; p < 4; p++)
        vb[p] = *(const float4*)&B[(size_t)(b_k + p * 8) * N + bn + b_n];
    #pragma unroll
    for (int p = 0; p < 4; p++) {
        uint32_t* d = &As[(a_m + p * 32) * ASTR + a_k];
        d[0] = f2tf(va[p].x); d[1] = f2tf(va[p].y);
        d[2] = f2tf(va[p].z); d[3] = f2tf(va[p].w);
    }
    #pragma unroll
    for (int p = 0; p < 4; p++) {
        uint32_t* d = &Bs[(b_k + p * 8) * BSTR + b_n];
        d[0] = f2tf(vb[p].x); d[1] = f2tf(vb[p].y);
        d[2] = f2tf(vb[p].z); d[3] = f2tf(vb[p].w);
    }
    __syncthreads();

    for (int kt = 0; kt < nkt; kt++) {
        const int cur = kt & 1;
        // prefetch next tile from global
        if (kt + 1 < nkt) {
            const int k0 = (kt + 1) * GBK;
            #pragma unroll
            for (int p = 0; p < 4; p++)
                va[p] = *(const float4*)&A[(size_t)(bm + a_m + p * 32) * K + k0 + a_k];
            #pragma unroll
            for (int p = 0; p < 4; p++)
                vb[p] = *(const float4*)&B[(size_t)(k0 + b_k + p * 8) * N + bn + b_n];
        }

        const uint32_t* Ac = As + cur * ASZ;
        const uint32_t* Bc = Bs + cur * BSZ;

        #pragma unroll
        for (int kk = 0; kk < GBK / 8; kk++) {
            const int kr = kk * 8;
            uint32_t af[2][4], bf[8][2];
            #pragma unroll
            for (int mt = 0; mt < 2; mt++) {
                const int m0 = warp_m * 32 + mt * 16;
                af[mt][0] = Ac[(m0 + g)     * ASTR + kr + l4];
                af[mt][1] = Ac[(m0 + g + 8) * ASTR + kr + l4];
                af[mt][2] = Ac[(m0 + g)     * ASTR + kr + l4 + 4];
                af[mt][3] = Ac[(m0 + g + 8) * ASTR + kr + l4 + 4];
            }
            #pragma unroll
            for (int nt = 0; nt < 8; nt++) {
                const int n0 = warp_n * 64 + nt * 8;
                bf[nt][0] = Bc[(kr + l4)     * BSTR + n0 + g];
                bf[nt][1] = Bc[(kr + l4 + 4) * BSTR + n0 + g];
            }
            #pragma unroll
            for (int mt = 0; mt < 2; mt++)
                #pragma unroll
                for (int nt = 0; nt < 8; nt++)
                    mma_tf32(acc[mt][nt], af[mt], bf[nt]);
        }

        // stage prefetched tile into the other buffer
        if (kt + 1 < nkt) {
            const int nxt = (kt + 1) & 1;
            uint32_t* An = As + nxt * ASZ;
            uint32_t* Bn = Bs + nxt * BSZ;
            #pragma unroll
            for (int p = 0; p < 4; p++) {
                uint32_t* d = &An[(a_m + p * 32) * ASTR + a_k];
                d[0] = f2tf(va[p].x); d[1] = f2tf(va[p].y);
                d[2] = f2tf(va[p].z); d[3] = f2tf(va[p].w);
            }
            #pragma unroll
            for (int p = 0; p < 4; p++) {
                uint32_t* d = &Bn[(b_k + p * 8) * BSTR + b_n];
                d[0] = f2tf(vb[p].x); d[1] = f2tf(vb[p].y);
                d[2] = f2tf(vb[p].z); d[3] = f2tf(vb[p].w);
            }
        }
        __syncthreads();
    }

    // epilogue: c0/c1 at (row=g, col=2*l4, 2*l4+1); c2/c3 at row=g+8
    #pragma unroll
    for (int mt = 0; mt < 2; mt++) {
        const int row0 = bm + warp_m * 32 + mt * 16 + g;
        #pragma unroll
        for (int nt = 0; nt < 8; nt++) {
            const int col = bn + warp_n * 64 + nt * 8 + 2 * l4;
            *(float2*)&C[(size_t)row0 * N + col] =
                make_float2(acc[mt][nt][0], acc[mt][nt][1]);
            *(float2*)&C[(size_t)(row0 + 8) * N + col] =
                make_float2(acc[mt][nt][2], acc[mt][nt][3]);
        }
    }
}

// ---------------------------------------------------------------------------
// RoPE in-place on q (heads 0..15) and k (heads 16..19) slices of g_qkv.
// ---------------------------------------------------------------------------
__global__ void rope_kernel(float* __restrict__ qkv)
{
    const int bs   = blockIdx.x;            // 0..4095
    const int head = blockIdx.y;            // 0..19
    const int d    = threadIdx.x;           // 0..63
    const int s    = bs & (SS - 1);

    float* base = qkv + (size_t)bs * QKVW +
                  (head < HH ? head * DD : HH * DD + (head - HH) * DD);

    const float inv_freq = exp2f(-(float)d * 0.311430758895690262f);
    const float ang = (float)s * inv_freq;
    float sn, cs;
    sincosf(ang, &sn, &cs);

    const float x0 = base[d];
    const float x1 = base[d + 64];
    base[d]      = x0 * cs - x1 * sn;
    base[d + 64] = x1 * cs + x0 * sn;
}

// ---------------------------------------------------------------------------
// Windowed causal GQA attention. One CTA per (b, h, 32-query tile).
// ---------------------------------------------------------------------------
#define BQ 32
#define SKSTRIDE 545   // max keys 544, +1 pad

__global__ void __launch_bounds__(256) attn_kernel(
    const float* __restrict__ qkv, float* __restrict__ out)
{
    extern __shared__ float sm[];
    float* Qs  = sm;                       // [32][132]
    float* KVs = Qs + 32 * 132;            // [32][132]
    float* Sc  = KVs + 32 * 132;           // [32][545]

    const int tid = threadIdx.x;
    const int b   = blockIdx.z;
    const int h   = blockIdx.y;
    const int q0  = blockIdx.x * BQ;
    const int g   = h >> 2;                // kv head
    const float scale = 0.088388347648318447f;  // 1/sqrt(128)

    for (int idx = tid; idx < BQ * DD; idx += 256) {
        int qi = idx >> 7, d = idx & 127;
        Qs[qi * 132 + d] =
            qkv[((size_t)(b * SS + q0 + qi)) * QKVW + h * DD + d] * scale;
    }

    const int js = max(0, q0 - WINW);
    const int nk = q0 + BQ - js;           // <= 544
    __syncthreads();

    // ---- score phase ----
    const int tq = (tid >> 4) << 1;
    const int tk = (tid & 15) << 1;
    for (int kt = 0; kt < nk; kt += 32) {
        for (int idx = tid; idx < 32 * DD; idx += 256) {
            int kj = idx >> 7, d = idx & 127;
            KVs[kj * 132 + d] =
                qkv[((size_t)(b * SS + js + kt + kj)) * QKVW + HH * DD + g * DD + d];
        }
        __syncthreads();

        float a00 = 0.f, a01 = 0.f, a10 = 0.f, a11 = 0.f;
        #pragma unroll 8
        for (int d = 0; d < DD; d++) {
            float qa = Qs[tq * 132 + d];
            float qb = Qs[(tq + 1) * 132 + d];
            float ka = KVs[tk * 132 + d];
            float kb = KVs[(tk + 1) * 132 + d];
            a00 += qa * ka; a01 += qa * kb;
            a10 += qb * ka; a11 += qb * kb;
        }
        const int i0 = q0 + tq, i1 = i0 + 1;
        const int j0 = js + kt + tk, j1 = j0 + 1;
        Sc[tq * SKSTRIDE + kt + tk]           = (j0 <= i0 && i0 - j0 < WINW) ? a00 : -1e30f;
        Sc[tq * SKSTRIDE + kt + tk + 1]       = (j1 <= i0 && i0 - j1 < WINW) ? a01 : -1e30f;
        Sc[(tq + 1) * SKSTRIDE + kt + tk]     = (j0 <= i1 && i1 - j0 < WINW) ? a10 : -1e30f;
        Sc[(tq + 1) * SKSTRIDE + kt + tk + 1] = (j1 <= i1 && i1 - j1 < WINW) ? a11 : -1e30f;
        __syncthreads();
    }

    // ---- softmax ----
    const int warp = tid >> 5, lane = tid & 31;
    for (int row = warp; row < BQ; row += 8) {
        float m = -1e30f;
        for (int j = lane; j < nk; j += 32) m = fmaxf(m, Sc[row * SKSTRIDE + j]);
        #pragma unroll
        for (int o = 16; o; o >>= 1) m = fmaxf(m, __shfl_xor_sync(0xffffffffu, m, o));
        float ssum = 0.f;
        for (int j = lane; j < nk; j += 32) {
            float e = __expf(Sc[row * SKSTRIDE + j] - m);
            Sc[row * SKSTRIDE + j] = e;
            ssum += e;
        }
        #pragma unroll
        for (int o = 16; o; o >>= 1) ssum += __shfl_xor_sync(0xffffffffu, ssum, o);
        float inv = 1.0f / ssum;
        for (int j = lane; j < nk; j += 32) Sc[row * SKSTRIDE + j] *= inv;
    }
    __syncthreads();

    // ---- PV phase ----
    const int qi0 = (tid & 15) << 1;
    const int dc  = (tid >> 4) << 3;
    float acc[2][8];
    #pragma unroll
    for (int r = 0; r < 2; r++)
        #pragma unroll
        for (int j = 0; j < 8; j++) acc[r][j] = 0.f;

    for (int kt = 0; kt < nk; kt += 32) {
        for (int idx = tid; idx < 32 * DD; idx += 256) {
            int kj = idx >> 7, d = idx & 127;
            KVs[kj * 132 + d] =
                qkv[((size_t)(b * SS + js + kt + kj)) * QKVW + (HH + KVH) * DD + g * DD + d];
        }
        __syncthreads();
        #pragma unroll 4
        for (int kj = 0; kj < 32; kj++) {
            float p0 = Sc[qi0 * SKSTRIDE + kt + kj];
            float p1 = Sc[(qi0 + 1) * SKSTRIDE + kt + kj];
            #pragma unroll
            for (int j = 0; j < 8; j++) {
                float v = KVs[kj * 132 + dc + j];
                acc[0][j] += p0 * v;
                acc[1][j] += p1 * v;
            }
        }
        __syncthreads();
    }

    #pragma unroll
    for (int r = 0; r < 2; r++) {
        float* dst = out + ((size_t)(b * SS + q0 + qi0 + r)) * (HH * DD) + h * DD + dc;
        #pragma unroll
        for (int j = 0; j < 8; j++) dst[j] = acc[r][j];
    }
}

// ---------------------------------------------------------------------------
extern "C" void kernel_launch(void* const* d_in, const int* in_sizes, int n_in,
                              void* d_out, int out_size)
{
    const float* x     = (const float*)d_in[0];   // [2,2048,2048]
    const float* w_qkv = (const float*)d_in[1];   // [2048,3072]
    const float* w_o   = (const float*)d_in[2];   // [2048,2048]
    float* out = (float*)d_out;                    // [2,2048,2048]

    float* qkv_ptr  = nullptr;
    float* attn_ptr = nullptr;
    cudaGetSymbolAddress((void**)&qkv_ptr,  g_qkv);
    cudaGetSymbolAddress((void**)&attn_ptr, g_attn);

    const int GEMM_SMEM = (2 * ASZ + 2 * BSZ) * (int)sizeof(uint32_t);  // ~71.7 KB
    cudaFuncSetAttribute(gemm_tf32_kernel,
                         cudaFuncAttributeMaxDynamicSharedMemorySize, GEMM_SMEM);

    const int ATTN_SMEM = (32 * 132 + 32 * 132 + 32 * SKSTRIDE) * (int)sizeof(float);
    cudaFuncSetAttribute(attn_kernel,
                         cudaFuncAttributeMaxDynamicSharedMemorySize, ATTN_SMEM);

    // 1) QKV projection: [4096,2048] @ [2048,3072]
    {
        dim3 grid(QKVW / 128, NROWS / 128);
        gemm_tf32_kernel<<<grid, 256, GEMM_SMEM>>>(x, w_qkv, qkv_ptr, NROWS, QKVW, EE);
    }
    // 2) RoPE in-place on q,k
    {
        dim3 grid(NROWS, HH + KVH);
        rope_kernel<<<grid, 64>>>(qkv_ptr);
    }
    // 3) Windowed GQA attention
    {
        dim3 grid(SS / BQ, HH, BB);
        attn_kernel<<<grid, 256, ATTN_SMEM>>>(qkv_ptr, attn_ptr);
    }
    // 4) Output projection: [4096,2048] @ [2048,2048]
    {
        dim3 grid(EE / 128, NROWS / 128);
        gemm_tf32_kernel<<<grid, 256, GEMM_SMEM>>>(attn_ptr, w_o, out, NROWS, EE, EE);
    }
}

// round 3
// speedup vs baseline: 3.5999x; 2.0416x over previous
#include <cuda_runtime.h>
#include <math.h>
#include <stdint.h>

// Problem constants
#define BB   2
#define SS   2048
#define EE   2048
#define HH   16
#define KVH  4
#define DD   128
#define WINW 512
#define QKVW ((HH + 2*KVH) * DD)   // 3072
#define NROWS (BB * SS)            // 4096

__device__ float g_qkv[(size_t)NROWS * QKVW];       // 4096 x 3072
__device__ float g_attn[(size_t)NROWS * HH * DD];   // 4096 x 2048

__device__ __forceinline__ uint32_t f2tf(float x) {
    uint32_t r;
    asm volatile("cvt.rna.tf32.f32 %0, %1;" : "=r"(r) : "f"(x));
    return r;
}

__device__ __forceinline__ void mma_tf32(float* c, const uint32_t* a, const uint32_t* b) {
    asm volatile(
        "mma.sync.aligned.m16n8k8.row.col.f32.tf32.tf32.f32 "
        "{%0,%1,%2,%3}, {%4,%5,%6,%7}, {%8,%9}, {%0,%1,%2,%3};\n"
        : "+f"(c[0]), "+f"(c[1]), "+f"(c[2]), "+f"(c[3])
        : "r"(a[0]), "r"(a[1]), "r"(a[2]), "r"(a[3]), "r"(b[0]), "r"(b[1]));
}

// ---------------------------------------------------------------------------
// TF32 tensor-core GEMM: C[M,N] = A[M,K] * B[K,N]  (validated round 2)
// ---------------------------------------------------------------------------
#define GBK 32
#define ASTR 36
#define BSTR 136
#define ASZ (128 * ASTR)
#define BSZ (GBK * BSTR)

__global__ void __launch_bounds__(256, 2) gemm_tf32_kernel(
    const float* __restrict__ A, const float* __restrict__ B,
    float* __restrict__ C, int M, int N, int K)
{
    extern __shared__ uint32_t smu[];
    uint32_t* As = smu;
    uint32_t* Bs = smu + 2 * ASZ;

    const int tid    = threadIdx.x;
    const int warp   = tid >> 5;
    const int lane   = tid & 31;
    const int g      = lane >> 2;
    const int l4     = lane & 3;
    const int warp_m = warp >> 1;
    const int warp_n = warp & 1;
    const int bm     = blockIdx.y * 128;
    const int bn     = blockIdx.x * 128;

    const int a_m = tid >> 3;
    const int a_k = (tid & 7) << 2;
    const int b_k = tid >> 5;
    const int b_n = (tid & 31) << 2;

    float acc[2][8][4];
    #pragma unroll
    for (int mt = 0; mt < 2; mt++)
        #pragma unroll
        for (int nt = 0; nt < 8; nt++)
            #pragma unroll
            for (int i = 0; i < 4; i++) acc[mt][nt][i] = 0.f;

    const int nkt = K / GBK;
    float4 va[4], vb[4];

    #pragma unroll
    for (int p = 0; p < 4; p++)
        va[p] = *(const float4*)&A[(size_t)(bm + a_m + p * 32) * K + a_k];
    #pragma unroll
    for (int p = 0; p < 4; p++)
        vb[p] = *(const float4*)&B[(size_t)(b_k + p * 8) * N + bn + b_n];
    #pragma unroll
    for (int p = 0; p < 4; p++) {
        uint32_t* d = &As[(a_m + p * 32) * ASTR + a_k];
        d[0] = f2tf(va[p].x); d[1] = f2tf(va[p].y);
        d[2] = f2tf(va[p].z); d[3] = f2tf(va[p].w);
    }
    #pragma unroll
    for (int p = 0; p < 4; p++) {
        uint32_t* d = &Bs[(b_k + p * 8) * BSTR + b_n];
        d[0] = f2tf(vb[p].x); d[1] = f2tf(vb[p].y);
        d[2] = f2tf(vb[p].z); d[3] = f2tf(vb[p].w);
    }
    __syncthreads();

    for (int kt = 0; kt < nkt; kt++) {
        const int cur = kt & 1;
        if (kt + 1 < nkt) {
            const int k0 = (kt + 1) * GBK;
            #pragma unroll
            for (int p = 0; p < 4; p++)
                va[p] = *(const float4*)&A[(size_t)(bm + a_m + p * 32) * K + k0 + a_k];
            #pragma unroll
            for (int p = 0; p < 4; p++)
                vb[p] = *(const float4*)&B[(size_t)(k0 + b_k + p * 8) * N + bn + b_n];
        }

        const uint32_t* Ac = As + cur * ASZ;
        const uint32_t* Bc = Bs + cur * BSZ;

        #pragma unroll
        for (int kk = 0; kk < GBK / 8; kk++) {
            const int kr = kk * 8;
            uint32_t af[2][4], bf[8][2];
            #pragma unroll
            for (int mt = 0; mt < 2; mt++) {
                const int m0 = warp_m * 32 + mt * 16;
                af[mt][0] = Ac[(m0 + g)     * ASTR + kr + l4];
                af[mt][1] = Ac[(m0 + g + 8) * ASTR + kr + l4];
                af[mt][2] = Ac[(m0 + g)     * ASTR + kr + l4 + 4];
                af[mt][3] = Ac[(m0 + g + 8) * ASTR + kr + l4 + 4];
            }
            #pragma unroll
            for (int nt = 0; nt < 8; nt++) {
                const int n0 = warp_n * 64 + nt * 8;
                bf[nt][0] = Bc[(kr + l4)     * BSTR + n0 + g];
                bf[nt][1] = Bc[(kr + l4 + 4) * BSTR + n0 + g];
            }
            #pragma unroll
            for (int mt = 0; mt < 2; mt++)
                #pragma unroll
                for (int nt = 0; nt < 8; nt++)
                    mma_tf32(acc[mt][nt], af[mt], bf[nt]);
        }

        if (kt + 1 < nkt) {
            const int nxt = (kt + 1) & 1;
            uint32_t* An = As + nxt * ASZ;
            uint32_t* Bn = Bs + nxt * BSZ;
            #pragma unroll
            for (int p = 0; p < 4; p++) {
                uint32_t* d = &An[(a_m + p * 32) * ASTR + a_k];
                d[0] = f2tf(va[p].x); d[1] = f2tf(va[p].y);
                d[2] = f2tf(va[p].z); d[3] = f2tf(va[p].w);
            }
            #pragma unroll
            for (int p = 0; p < 4; p++) {
                uint32_t* d = &Bn[(b_k + p * 8) * BSTR + b_n];
                d[0] = f2tf(vb[p].x); d[1] = f2tf(vb[p].y);
                d[2] = f2tf(vb[p].z); d[3] = f2tf(vb[p].w);
            }
        }
        __syncthreads();
    }

    #pragma unroll
    for (int mt = 0; mt < 2; mt++) {
        const int row0 = bm + warp_m * 32 + mt * 16 + g;
        #pragma unroll
        for (int nt = 0; nt < 8; nt++) {
            const int col = bn + warp_n * 64 + nt * 8 + 2 * l4;
            *(float2*)&C[(size_t)row0 * N + col] =
                make_float2(acc[mt][nt][0], acc[mt][nt][1]);
            *(float2*)&C[(size_t)(row0 + 8) * N + col] =
                make_float2(acc[mt][nt][2], acc[mt][nt][3]);
        }
    }
}

// ---------------------------------------------------------------------------
// RoPE in-place on q,k slices of g_qkv.
// ---------------------------------------------------------------------------
__global__ void rope_kernel(float* __restrict__ qkv)
{
    const int bs   = blockIdx.x;
    const int head = blockIdx.y;
    const int d    = threadIdx.x;
    const int s    = bs & (SS - 1);

    float* base = qkv + (size_t)bs * QKVW +
                  (head < HH ? head * DD : HH * DD + (head - HH) * DD);

    const float inv_freq = exp2f(-(float)d * 0.311430758895690262f);
    const float ang = (float)s * inv_freq;
    float sn, cs;
    sincosf(ang, &sn, &cs);

    const float x0 = base[d];
    const float x1 = base[d + 64];
    base[d]      = x0 * cs - x1 * sn;
    base[d + 64] = x1 * cs + x0 * sn;
}

// ---------------------------------------------------------------------------
// TF32 tensor-core flash attention with 512-window causal mask.
// CTA = (b, h, 128-query tile); 8 warps; warp owns 16 query rows.
// Key tiles of 64. K in smem stride 132, V stride 136 (conflict-free frags).
// ---------------------------------------------------------------------------
#define BQ 128
#define KT 64
#define KSTR 132
#define VSTR 136
#define MASKVAL -3.0e38f

__global__ void __launch_bounds__(256) attn_tc_kernel(
    const float* __restrict__ qkv, float* __restrict__ out)
{
    extern __shared__ uint32_t smem[];
    uint32_t* Ks = smem;                 // [64][132]
    uint32_t* Vs = smem + 64 * KSTR;     // [64][136]

    const int tid  = threadIdx.x;
    const int warp = tid >> 5;
    const int lane = tid & 31;
    const int g    = lane >> 2;
    const int l4   = lane & 3;
    const int b    = blockIdx.z;
    const int h    = blockIdx.y;
    const int q0   = blockIdx.x * BQ;
    const int gkv  = h >> 2;
    const float scale = 0.088388347648318447f;   // 1/sqrt(128)

    // ---- stage Q (two 64-row passes through Ks), extract fragments ----
    uint32_t qf[16][4];
    #pragma unroll
    for (int pass = 0; pass < 2; pass++) {
        for (int idx = tid; idx < 64 * 32; idx += 256) {
            int r = idx >> 5, c4 = (idx & 31) << 2;
            float4 v = *(const float4*)&qkv[(size_t)(b * SS + q0 + pass * 64 + r) * QKVW
                                            + h * DD + c4];
            uint4 u;
            u.x = f2tf(v.x * scale); u.y = f2tf(v.y * scale);
            u.z = f2tf(v.z * scale); u.w = f2tf(v.w * scale);
            *(uint4*)&Ks[r * KSTR + c4] = u;
        }
        __syncthreads();
        if ((warp >> 2) == pass) {
            const int lr = (warp & 3) * 16;
            #pragma unroll
            for (int k = 0; k < 16; k++) {
                qf[k][0] = Ks[(lr + g)     * KSTR + k * 8 + l4];
                qf[k][1] = Ks[(lr + g + 8) * KSTR + k * 8 + l4];
                qf[k][2] = Ks[(lr + g)     * KSTR + k * 8 + l4 + 4];
                qf[k][3] = Ks[(lr + g + 8) * KSTR + k * 8 + l4 + 4];
            }
        }
        __syncthreads();
    }

    // online softmax state (rows i_a = base+g, i_b = base+g+8)
    float o[16][4];
    #pragma unroll
    for (int dt = 0; dt < 16; dt++)
        #pragma unroll
        for (int i = 0; i < 4; i++) o[dt][i] = 0.f;
    float m_a = -1e30f, m_b = -1e30f, l_a = 0.f, l_b = 0.f;

    const int i_lo = q0 + warp * 16;
    const int i_a  = i_lo + g;
    const int i_b  = i_a + 8;
    const int js   = max(0, q0 - WINW);

    for (int kt0 = js; kt0 < q0 + BQ; kt0 += KT) {
        // ---- stage K, V tiles (tf32) ----
        for (int idx = tid; idx < 64 * 32; idx += 256) {
            int r = idx >> 5, c4 = (idx & 31) << 2;
            size_t rowbase = (size_t)(b * SS + kt0 + r) * QKVW + HH * DD + gkv * DD;
            float4 kv = *(const float4*)&qkv[rowbase + c4];
            uint4 uk;
            uk.x = f2tf(kv.x); uk.y = f2tf(kv.y); uk.z = f2tf(kv.z); uk.w = f2tf(kv.w);
            *(uint4*)&Ks[r * KSTR + c4] = uk;
            float4 vv = *(const float4*)&qkv[rowbase + KVH * DD + c4];
            uint4 uv;
            uv.x = f2tf(vv.x); uv.y = f2tf(vv.y); uv.z = f2tf(vv.z); uv.w = f2tf(vv.w);
            *(uint4*)&Vs[r * VSTR + c4] = uv;
        }
        __syncthreads();

        // ---- S = Q K^T ----
        float s[8][4];
        #pragma unroll
        for (int nt = 0; nt < 8; nt++)
            #pragma unroll
            for (int i = 0; i < 4; i++) s[nt][i] = 0.f;

        #pragma unroll
        for (int k = 0; k < 16; k++) {
            #pragma unroll
            for (int nt = 0; nt < 8; nt++) {
                uint32_t bf[2];
                bf[0] = Ks[(nt * 8 + g) * KSTR + k * 8 + l4];
                bf[1] = Ks[(nt * 8 + g) * KSTR + k * 8 + l4 + 4];
                mma_tf32(s[nt], qf[k], bf);
            }
        }

        // ---- mask ----
        #pragma unroll
        for (int nt = 0; nt < 8; nt++) {
            const int j0 = kt0 + nt * 8;
            const bool allvalid = (j0 + 7 <= i_lo) && (i_lo + 15 - j0 < WINW);
            if (!allvalid) {
                const int ja = j0 + 2 * l4, jb = ja + 1;
                if (!(ja <= i_a && i_a - ja < WINW)) s[nt][0] = MASKVAL;
                if (!(jb <= i_a && i_a - jb < WINW)) s[nt][1] = MASKVAL;
                if (!(ja <= i_b && i_b - ja < WINW)) s[nt][2] = MASKVAL;
                if (!(jb <= i_b && i_b - jb < WINW)) s[nt][3] = MASKVAL;
            }
        }

        // ---- online softmax (per-row, quad-group reductions) ----
        float ta = MASKVAL, tb = MASKVAL;
        #pragma unroll
        for (int nt = 0; nt < 8; nt++) {
            ta = fmaxf(ta, fmaxf(s[nt][0], s[nt][1]));
            tb = fmaxf(tb, fmaxf(s[nt][2], s[nt][3]));
        }
        ta = fmaxf(ta, __shfl_xor_sync(0xffffffffu, ta, 1));
        ta = fmaxf(ta, __shfl_xor_sync(0xffffffffu, ta, 2));
        tb = fmaxf(tb, __shfl_xor_sync(0xffffffffu, tb, 1));
        tb = fmaxf(tb, __shfl_xor_sync(0xffffffffu, tb, 2));

        const float mna = fmaxf(m_a, ta);
        const float mnb = fmaxf(m_b, tb);
        const float alpha_a = __expf(m_a - mna);
        const float alpha_b = __expf(m_b - mnb);
        m_a = mna; m_b = mnb;

        float ra = 0.f, rb = 0.f;
        #pragma unroll
        for (int nt = 0; nt < 8; nt++) {
            s[nt][0] = __expf(s[nt][0] - m_a);
            s[nt][1] = __expf(s[nt][1] - m_a);
            s[nt][2] = __expf(s[nt][2] - m_b);
            s[nt][3] = __expf(s[nt][3] - m_b);
            ra += s[nt][0] + s[nt][1];
            rb += s[nt][2] + s[nt][3];
        }
        ra += __shfl_xor_sync(0xffffffffu, ra, 1);
        ra += __shfl_xor_sync(0xffffffffu, ra, 2);
        rb += __shfl_xor_sync(0xffffffffu, rb, 1);
        rb += __shfl_xor_sync(0xffffffffu, rb, 2);
        l_a = l_a * alpha_a + ra;
        l_b = l_b * alpha_b + rb;

        #pragma unroll
        for (int dt = 0; dt < 16; dt++) {
            o[dt][0] *= alpha_a; o[dt][1] *= alpha_a;
            o[dt][2] *= alpha_b; o[dt][3] *= alpha_b;
        }

        // ---- O += P V : shuffle P from C-layout to A-layout per 8-key chunk ----
        const int src0 = (lane & ~3) | (l4 >> 1);
        const int src1 = src0 + 2;
        const bool odd = (l4 & 1);
        #pragma unroll
        for (int nt = 0; nt < 8; nt++) {
            float u0 = __shfl_sync(0xffffffffu, s[nt][0], src0);
            float u1 = __shfl_sync(0xffffffffu, s[nt][1], src0);
            float w0 = __shfl_sync(0xffffffffu, s[nt][0], src1);
            float w1 = __shfl_sync(0xffffffffu, s[nt][1], src1);
            float x0 = __shfl_sync(0xffffffffu, s[nt][2], src0);
            float x1 = __shfl_sync(0xffffffffu, s[nt][3], src0);
            float y0 = __shfl_sync(0xffffffffu, s[nt][2], src1);
            float y1 = __shfl_sync(0xffffffffu, s[nt][3], src1);
            uint32_t ap[4];
            ap[0] = f2tf(odd ? u1 : u0);
            ap[1] = f2tf(odd ? x1 : x0);
            ap[2] = f2tf(odd ? w1 : w0);
            ap[3] = f2tf(odd ? y1 : y0);
            #pragma unroll
            for (int dt = 0; dt < 16; dt++) {
                uint32_t bf[2];
                bf[0] = Vs[(nt * 8 + l4)     * VSTR + dt * 8 + g];
                bf[1] = Vs[(nt * 8 + l4 + 4) * VSTR + dt * 8 + g];
                mma_tf32(o[dt], ap, bf);
            }
        }
        __syncthreads();
    }

    // ---- normalize + write out ----
    const float inv_a = 1.0f / l_a;
    const float inv_b = 1.0f / l_b;
    #pragma unroll
    for (int dt = 0; dt < 16; dt++) {
        const int col = h * DD + dt * 8 + 2 * l4;
        *(float2*)&out[(size_t)(b * SS + i_a) * (HH * DD) + col] =
            make_float2(o[dt][0] * inv_a, o[dt][1] * inv_a);
        *(float2*)&out[(size_t)(b * SS + i_b) * (HH * DD) + col] =
            make_float2(o[dt][2] * inv_b, o[dt][3] * inv_b);
    }
}

// ---------------------------------------------------------------------------
extern "C" void kernel_launch(void* const* d_in, const int* in_sizes, int n_in,
                              void* d_out, int out_size)
{
    const float* x     = (const float*)d_in[0];
    const float* w_qkv = (const float*)d_in[1];
    const float* w_o   = (const float*)d_in[2];
    float* out = (float*)d_out;

    float* qkv_ptr  = nullptr;
    float* attn_ptr = nullptr;
    cudaGetSymbolAddress((void**)&qkv_ptr,  g_qkv);
    cudaGetSymbolAddress((void**)&attn_ptr, g_attn);

    const int GEMM_SMEM = (2 * ASZ + 2 * BSZ) * (int)sizeof(uint32_t);
    cudaFuncSetAttribute(gemm_tf32_kernel,
                         cudaFuncAttributeMaxDynamicSharedMemorySize, GEMM_SMEM);

    const int ATTN_SMEM = (64 * KSTR + 64 * VSTR) * (int)sizeof(uint32_t);
    cudaFuncSetAttribute(attn_tc_kernel,
                         cudaFuncAttributeMaxDynamicSharedMemorySize, ATTN_SMEM);

    // 1) QKV projection
    {
        dim3 grid(QKVW / 128, NROWS / 128);
        gemm_tf32_kernel<<<grid, 256, GEMM_SMEM>>>(x, w_qkv, qkv_ptr, NROWS, QKVW, EE);
    }
    // 2) RoPE
    {
        dim3 grid(NROWS, HH + KVH);
        rope_kernel<<<grid, 64>>>(qkv_ptr);
    }
    // 3) Flash attention (tensor cores)
    {
        dim3 grid(SS / BQ, HH, BB);
        attn_tc_kernel<<<grid, 256, ATTN_SMEM>>>(qkv_ptr, attn_ptr);
    }
    // 4) Output projection
    {
        dim3 grid(EE / 128, NROWS / 128);
        gemm_tf32_kernel<<<grid, 256, GEMM_SMEM>>>(attn_ptr, w_o, out, NROWS, EE, EE);
    }
}

// round 5
// speedup vs baseline: 3.7854x; 1.0515x over previous
#include <cuda_runtime.h>
#include <math.h>
#include <stdint.h>

// Problem constants
#define BB   2
#define SS   2048
#define EE   2048
#define HH   16
#define KVH  4
#define DD   128
#define WINW 512
#define QKVW ((HH + 2*KVH) * DD)   // 3072
#define NROWS (BB * SS)            // 4096

// Scratch (static device globals — allocation-free per harness rules)
__device__ float    g_qkv[(size_t)NROWS * QKVW];        // fp32 qkv (post-RoPE)
__device__ uint32_t g_attn[(size_t)NROWS * HH * DD];    // tf32 bits of attn out
__device__ uint32_t g_x32[(size_t)NROWS * EE];          // tf32 bits of x
__device__ uint32_t g_wqkv32[(size_t)EE * QKVW];        // tf32 bits of w_qkv [K][N]
__device__ uint32_t g_wo32[(size_t)EE * EE];            // tf32 bits of w_o   [K][N]

__device__ __forceinline__ uint32_t f2tf(float x) {
    uint32_t r;
    asm volatile("cvt.rna.tf32.f32 %0, %1;" : "=r"(r) : "f"(x));
    return r;
}

__device__ __forceinline__ void mma_tf32(float* c, const uint32_t* a, const uint32_t* b) {
    asm volatile(
        "mma.sync.aligned.m16n8k8.row.col.f32.tf32.tf32.f32 "
        "{%0,%1,%2,%3}, {%4,%5,%6,%7}, {%8,%9}, {%0,%1,%2,%3};\n"
        : "+f"(c[0]), "+f"(c[1]), "+f"(c[2]), "+f"(c[3])
        : "r"(a[0]), "r"(a[1]), "r"(a[2]), "r"(a[3]), "r"(b[0]), "r"(b[1]));
}

__device__ __forceinline__ void cp_async_16(uint32_t smem_addr, const void* gptr) {
    asm volatile("cp.async.cg.shared.global [%0], [%1], 16;" :: "r"(smem_addr), "l"(gptr));
}

// ---------------------------------------------------------------------------
// Prep: fp32 -> tf32 bits (rna), elementwise, vectorized.
// ---------------------------------------------------------------------------
__global__ void cvt_tf32_kernel(const float* __restrict__ in, uint32_t* __restrict__ outp, int n4)
{
    int i = blockIdx.x * blockDim.x + threadIdx.x;
    if (i < n4) {
        float4 v = ((const float4*)in)[i];
        uint4 u;
        u.x = f2tf(v.x); u.y = f2tf(v.y); u.z = f2tf(v.z); u.w = f2tf(v.w);
        ((uint4*)outp)[i] = u;
    }
}

// ---------------------------------------------------------------------------
// TF32 mma.sync GEMM v2: C[M,N] = A[M,K] * B[K,N]
// Operands are pre-converted tf32 bits — the mainloop does NO cvt and NO
// register staging: 3-stage cp.async pipeline, one __syncthreads per k-tile.
// BM=BN=128, BK=32, 256 threads, 8 warps (4x2), warp tile 32x64.
// ---------------------------------------------------------------------------
#define GBK   32
#define ASTR  36                    // As[m][k] stride: frag banks 4g+l4, conflict-free
#define BSTR  136                   // Bs[k][n] stride: frag banks 8*l4+g, conflict-free
#define ATILE (128 * ASTR)          // words
#define BTILE (GBK * BSTR)          // words
#define STG   (ATILE + BTILE)       // words per stage = 8960 (35840 B)
#define NSTAGE 3
#define GEMM_SMEM_BYTES (NSTAGE * STG * 4)   // 107520 B

__global__ void __launch_bounds__(256, 2) gemm_tf32_v2(
    const uint32_t* __restrict__ A, const uint32_t* __restrict__ B,
    float* __restrict__ C, int M, int N, int K)
{
    extern __shared__ uint32_t smu[];
    uint32_t smem_base;
    asm("{ .reg .u64 t; cvta.to.shared.u64 t, %1; cvt.u32.u64 %0, t; }"
        : "=r"(smem_base) : "l"(smu));

    const int tid    = threadIdx.x;
    const int warp   = tid >> 5;
    const int lane   = tid & 31;
    const int g      = lane >> 2;
    const int l4     = lane & 3;
    const int warp_m = warp >> 1;
    const int warp_n = warp & 1;
    const int bm     = blockIdx.y * 128;
    const int bn     = blockIdx.x * 128;

    // A loader: idx = tid + i*256 (i<4): row=idx>>3, col4=(idx&7)*4
    const int a_r  = tid >> 3;
    const int a_c4 = (tid & 7) << 2;
    // B loader: row=idx>>5, col4=(idx&31)*4
    const int b_r  = tid >> 5;
    const int b_c4 = (tid & 31) << 2;

    const int ntiles = K / GBK;

    // issue stage `s` (k-tile index s) into buffer s % NSTAGE
    auto issue_stage = [&](int s) {
        const uint32_t buf = smem_base + (uint32_t)(s % NSTAGE) * (STG * 4);
        const int k0 = s * GBK;
        const uint32_t sa = buf;
        #pragma unroll
        for (int i = 0; i < 4; i++) {
            const int r  = a_r + i * 32;
            cp_async_16(sa + (uint32_t)(r * ASTR + a_c4) * 4,
                        &A[(size_t)(bm + r) * K + k0 + a_c4]);
        }
        const uint32_t sb = buf + ATILE * 4;
        #pragma unroll
        for (int i = 0; i < 4; i++) {
            const int r = b_r + i * 8;
            cp_async_16(sb + (uint32_t)(r * BSTR + b_c4) * 4,
                        &B[(size_t)(k0 + r) * N + bn + b_c4]);
        }
        asm volatile("cp.async.commit_group;" ::: "memory");
    };

    float acc[2][8][4];
    #pragma unroll
    for (int mt = 0; mt < 2; mt++)
        #pragma unroll
        for (int nt = 0; nt < 8; nt++)
            #pragma unroll
            for (int i = 0; i < 4; i++) acc[mt][nt][i] = 0.f;

    issue_stage(0);
    issue_stage(1);

    for (int it = 0; it < ntiles; it++) {
        if (it + 1 < ntiles)
            asm volatile("cp.async.wait_group 1;" ::: "memory");
        else
            asm volatile("cp.async.wait_group 0;" ::: "memory");
        __syncthreads();

        if (it + 2 < ntiles) issue_stage(it + 2);

        const uint32_t* buf = smu + (size_t)(it % NSTAGE) * STG;
        const uint32_t* Ac  = buf;
        const uint32_t* Bc  = buf + ATILE;

        // warp-local base pointers (hoist address math out of inner loops)
        const uint32_t* Aw = Ac + (warp_m * 32 + g) * ASTR + l4;
        const uint32_t* Bw = Bc + l4 * BSTR + warp_n * 64 + g;

        #pragma unroll
        for (int kk = 0; kk < GBK / 8; kk++) {
            const int kr = kk * 8;
            uint32_t af[2][4], bf[8][2];
            #pragma unroll
            for (int mt = 0; mt < 2; mt++) {
                const uint32_t* p = Aw + mt * 16 * ASTR + kr;
                af[mt][0] = p[0];
                af[mt][1] = p[8 * ASTR];
                af[mt][2] = p[4];
                af[mt][3] = p[8 * ASTR + 4];
            }
            #pragma unroll
            for (int nt = 0; nt < 8; nt++) {
                const uint32_t* p = Bw + kr * BSTR + nt * 8;
                bf[nt][0] = p[0];
                bf[nt][1] = p[4 * BSTR];
            }
            #pragma unroll
            for (int mt = 0; mt < 2; mt++)
                #pragma unroll
                for (int nt = 0; nt < 8; nt++)
                    mma_tf32(acc[mt][nt], af[mt], bf[nt]);
        }
        __syncthreads();
    }

    #pragma unroll
    for (int mt = 0; mt < 2; mt++) {
        const int row0 = bm + warp_m * 32 + mt * 16 + g;
        #pragma unroll
        for (int nt = 0; nt < 8; nt++) {
            const int col = bn + warp_n * 64 + nt * 8 + 2 * l4;
            *(float2*)&C[(size_t)row0 * N + col] =
                make_float2(acc[mt][nt][0], acc[mt][nt][1]);
            *(float2*)&C[(size_t)(row0 + 8) * N + col] =
                make_float2(acc[mt][nt][2], acc[mt][nt][3]);
        }
    }
}

// ---------------------------------------------------------------------------
// RoPE in-place on q,k slices of g_qkv.
// ---------------------------------------------------------------------------
__global__ void rope_kernel(float* __restrict__ qkv)
{
    const int bs   = blockIdx.x;
    const int head = blockIdx.y;
    const int d    = threadIdx.x;
    const int s    = bs & (SS - 1);

    float* base = qkv + (size_t)bs * QKVW +
                  (head < HH ? head * DD : HH * DD + (head - HH) * DD);

    const float inv_freq = exp2f(-(float)d * 0.311430758895690262f);
    const float ang = (float)s * inv_freq;
    float sn, cs;
    sincosf(ang, &sn, &cs);

    const float x0 = base[d];
    const float x1 = base[d + 64];
    base[d]      = x0 * cs - x1 * sn;
    base[d + 64] = x1 * cs + x0 * sn;
}

// ---------------------------------------------------------------------------
// TF32 mma.sync flash attention (validated round 3). Output = tf32 bits.
// ---------------------------------------------------------------------------
#define BQ 128
#define KT 64
#define KSTR 132
#define VSTR 136
#define MASKVAL -3.0e38f

__global__ void __launch_bounds__(256) attn_tc_kernel(
    const float* __restrict__ qkv, uint32_t* __restrict__ out)
{
    extern __shared__ uint32_t smem[];
    uint32_t* Ks = smem;
    uint32_t* Vs = smem + 64 * KSTR;

    const int tid  = threadIdx.x;
    const int warp = tid >> 5;
    const int lane = tid & 31;
    const int g    = lane >> 2;
    const int l4   = lane & 3;
    const int b    = blockIdx.z;
    const int h    = blockIdx.y;
    const int q0   = blockIdx.x * BQ;
    const int gkv  = h >> 2;
    const float scale = 0.088388347648318447f;

    uint32_t qf[16][4];
    #pragma unroll
    for (int pass = 0; pass < 2; pass++) {
        for (int idx = tid; idx < 64 * 32; idx += 256) {
            int r = idx >> 5, c4 = (idx & 31) << 2;
            float4 v = *(const float4*)&qkv[(size_t)(b * SS + q0 + pass * 64 + r) * QKVW
                                            + h * DD + c4];
            uint4 u;
            u.x = f2tf(v.x * scale); u.y = f2tf(v.y * scale);
            u.z = f2tf(v.z * scale); u.w = f2tf(v.w * scale);
            *(uint4*)&Ks[r * KSTR + c4] = u;
        }
        __syncthreads();
        if ((warp >> 2) == pass) {
            const int lr = (warp & 3) * 16;
            #pragma unroll
            for (int k = 0; k < 16; k++) {
                qf[k][0] = Ks[(lr + g)     * KSTR + k * 8 + l4];
                qf[k][1] = Ks[(lr + g + 8) * KSTR + k * 8 + l4];
                qf[k][2] = Ks[(lr + g)     * KSTR + k * 8 + l4 + 4];
                qf[k][3] = Ks[(lr + g + 8) * KSTR + k * 8 + l4 + 4];
            }
        }
        __syncthreads();
    }

    float o[16][4];
    #pragma unroll
    for (int dt = 0; dt < 16; dt++)
        #pragma unroll
        for (int i = 0; i < 4; i++) o[dt][i] = 0.f;
    float m_a = -1e30f, m_b = -1e30f, l_a = 0.f, l_b = 0.f;

    const int i_lo = q0 + warp * 16;
    const int i_a  = i_lo + g;
    const int i_b  = i_a + 8;
    const int js   = max(0, q0 - WINW);

    for (int kt0 = js; kt0 < q0 + BQ; kt0 += KT) {
        for (int idx = tid; idx < 64 * 32; idx += 256) {
            int r = idx >> 5, c4 = (idx & 31) << 2;
            size_t rowbase = (size_t)(b * SS + kt0 + r) * QKVW + HH * DD + gkv * DD;
            float4 kv = *(const float4*)&qkv[rowbase + c4];
            uint4 uk;
            uk.x = f2tf(kv.x); uk.y = f2tf(kv.y); uk.z = f2tf(kv.z); uk.w = f2tf(kv.w);
            *(uint4*)&Ks[r * KSTR + c4] = uk;
            float4 vv = *(const float4*)&qkv[rowbase + KVH * DD + c4];
            uint4 uv;
            uv.x = f2tf(vv.x); uv.y = f2tf(vv.y); uv.z = f2tf(vv.z); uv.w = f2tf(vv.w);
            *(uint4*)&Vs[r * VSTR + c4] = uv;
        }
        __syncthreads();

        float s[8][4];
        #pragma unroll
        for (int nt = 0; nt < 8; nt++)
            #pragma unroll
            for (int i = 0; i < 4; i++) s[nt][i] = 0.f;

        #pragma unroll
        for (int k = 0; k < 16; k++) {
            #pragma unroll
            for (int nt = 0; nt < 8; nt++) {
                uint32_t bf[2];
                bf[0] = Ks[(nt * 8 + g) * KSTR + k * 8 + l4];
                bf[1] = Ks[(nt * 8 + g) * KSTR + k * 8 + l4 + 4];
                mma_tf32(s[nt], qf[k], bf);
            }
        }

        #pragma unroll
        for (int nt = 0; nt < 8; nt++) {
            const int j0 = kt0 + nt * 8;
            const bool allvalid = (j0 + 7 <= i_lo) && (i_lo + 15 - j0 < WINW);
            if (!allvalid) {
                const int ja = j0 + 2 * l4, jb = ja + 1;
                if (!(ja <= i_a && i_a - ja < WINW)) s[nt][0] = MASKVAL;
                if (!(jb <= i_a && i_a - jb < WINW)) s[nt][1] = MASKVAL;
                if (!(ja <= i_b && i_b - ja < WINW)) s[nt][2] = MASKVAL;
                if (!(jb <= i_b && i_b - jb < WINW)) s[nt][3] = MASKVAL;
            }
        }

        float ta = MASKVAL, tb = MASKVAL;
        #pragma unroll
        for (int nt = 0; nt < 8; nt++) {
            ta = fmaxf(ta, fmaxf(s[nt][0], s[nt][1]));
            tb = fmaxf(tb, fmaxf(s[nt][2], s[nt][3]));
        }
        ta = fmaxf(ta, __shfl_xor_sync(0xffffffffu, ta, 1));
        ta = fmaxf(ta, __shfl_xor_sync(0xffffffffu, ta, 2));
        tb = fmaxf(tb, __shfl_xor_sync(0xffffffffu, tb, 1));
        tb = fmaxf(tb, __shfl_xor_sync(0xffffffffu, tb, 2));

        const float mna = fmaxf(m_a, ta);
        const float mnb = fmaxf(m_b, tb);
        const float alpha_a = __expf(m_a - mna);
        const float alpha_b = __expf(m_b - mnb);
        m_a = mna; m_b = mnb;

        float ra = 0.f, rb = 0.f;
        #pragma unroll
        for (int nt = 0; nt < 8; nt++) {
            s[nt][0] = __expf(s[nt][0] - m_a);
            s[nt][1] = __expf(s[nt][1] - m_a);
            s[nt][2] = __expf(s[nt][2] - m_b);
            s[nt][3] = __expf(s[nt][3] - m_b);
            ra += s[nt][0] + s[nt][1];
            rb += s[nt][2] + s[nt][3];
        }
        ra += __shfl_xor_sync(0xffffffffu, ra, 1);
        ra += __shfl_xor_sync(0xffffffffu, ra, 2);
        rb += __shfl_xor_sync(0xffffffffu, rb, 1);
        rb += __shfl_xor_sync(0xffffffffu, rb, 2);
        l_a = l_a * alpha_a + ra;
        l_b = l_b * alpha_b + rb;

        #pragma unroll
        for (int dt = 0; dt < 16; dt++) {
            o[dt][0] *= alpha_a; o[dt][1] *= alpha_a;
            o[dt][2] *= alpha_b; o[dt][3] *= alpha_b;
        }

        const int src0 = (lane & ~3) | (l4 >> 1);
        const int src1 = src0 + 2;
        const bool odd = (l4 & 1);
        #pragma unroll
        for (int nt = 0; nt < 8; nt++) {
            float u0 = __shfl_sync(0xffffffffu, s[nt][0], src0);
            float u1 = __shfl_sync(0xffffffffu, s[nt][1], src0);
            float w0 = __shfl_sync(0xffffffffu, s[nt][0], src1);
            float w1 = __shfl_sync(0xffffffffu, s[nt][1], src1);
            float x0 = __shfl_sync(0xffffffffu, s[nt][2], src0);
            float x1 = __shfl_sync(0xffffffffu, s[nt][3], src0);
            float y0 = __shfl_sync(0xffffffffu, s[nt][2], src1);
            float y1 = __shfl_sync(0xffffffffu, s[nt][3], src1);
            uint32_t ap[4];
            ap[0] = f2tf(odd ? u1 : u0);
            ap[1] = f2tf(odd ? x1 : x0);
            ap[2] = f2tf(odd ? w1 : w0);
            ap[3] = f2tf(odd ? y1 : y0);
            #pragma unroll
            for (int dt = 0; dt < 16; dt++) {
                uint32_t bf[2];
                bf[0] = Vs[(nt * 8 + l4)     * VSTR + dt * 8 + g];
                bf[1] = Vs[(nt * 8 + l4 + 4) * VSTR + dt * 8 + g];
                mma_tf32(o[dt], ap, bf);
            }
        }
        __syncthreads();
    }

    const float inv_a = 1.0f / l_a;
    const float inv_b = 1.0f / l_b;
    #pragma unroll
    for (int dt = 0; dt < 16; dt++) {
        const int col = h * DD + dt * 8 + 2 * l4;
        *(uint2*)&out[(size_t)(b * SS + i_a) * (HH * DD) + col] =
            make_uint2(f2tf(o[dt][0] * inv_a), f2tf(o[dt][1] * inv_a));
        *(uint2*)&out[(size_t)(b * SS + i_b) * (HH * DD) + col] =
            make_uint2(f2tf(o[dt][2] * inv_b), f2tf(o[dt][3] * inv_b));
    }
}

// ---------------------------------------------------------------------------
extern "C" void kernel_launch(void* const* d_in, const int* in_sizes, int n_in,
                              void* d_out, int out_size)
{
    const float* x     = (const float*)d_in[0];
    const float* w_qkv = (const float*)d_in[1];
    const float* w_o   = (const float*)d_in[2];
    float* out = (float*)d_out;

    float*    qkv_ptr  = nullptr;
    uint32_t* attn_ptr = nullptr;
    uint32_t* x32_ptr  = nullptr;
    uint32_t* wqkv32   = nullptr;
    uint32_t* wo32     = nullptr;
    cudaGetSymbolAddress((void**)&qkv_ptr,  g_qkv);
    cudaGetSymbolAddress((void**)&attn_ptr, g_attn);
    cudaGetSymbolAddress((void**)&x32_ptr,  g_x32);
    cudaGetSymbolAddress((void**)&wqkv32,   g_wqkv32);
    cudaGetSymbolAddress((void**)&wo32,     g_wo32);

    cudaFuncSetAttribute(gemm_tf32_v2,
                         cudaFuncAttributeMaxDynamicSharedMemorySize, GEMM_SMEM_BYTES);
    const int ATTN_SMEM = (64 * KSTR + 64 * VSTR) * (int)sizeof(uint32_t);
    cudaFuncSetAttribute(attn_tc_kernel,
                         cudaFuncAttributeMaxDynamicSharedMemorySize, ATTN_SMEM);

    // 0) prep: convert all GEMM operands to tf32 bits (rna) once
    {
        int n4 = (NROWS * EE) / 4;
        cvt_tf32_kernel<<<(n4 + 255) / 256, 256>>>(x, x32_ptr, n4);
        n4 = (EE * QKVW) / 4;
        cvt_tf32_kernel<<<(n4 + 255) / 256, 256>>>(w_qkv, wqkv32, n4);
        n4 = (EE * EE) / 4;
        cvt_tf32_kernel<<<(n4 + 255) / 256, 256>>>(w_o, wo32, n4);
    }
    // 1) QKV projection: [4096,2048] @ [2048,3072]
    {
        dim3 grid(QKVW / 128, NROWS / 128);
        gemm_tf32_v2<<<grid, 256, GEMM_SMEM_BYTES>>>(x32_ptr, wqkv32, qkv_ptr,
                                                     NROWS, QKVW, EE);
    }
    // 2) RoPE
    {
        dim3 grid(NROWS, HH + KVH);
        rope_kernel<<<grid, 64>>>(qkv_ptr);
    }
    // 3) Flash attention (writes tf32 bits)
    {
        dim3 grid(SS / BQ, HH, BB);
        attn_tc_kernel<<<grid, 256, ATTN_SMEM>>>(qkv_ptr, attn_ptr);
    }
    // 4) Output projection: [4096,2048] @ [2048,2048]
    {
        dim3 grid(EE / 128, NROWS / 128);
        gemm_tf32_v2<<<grid, 256, GEMM_SMEM_BYTES>>>(attn_ptr, wo32, out,
                                                     NROWS, EE, EE);
    }
}

// round 6
// speedup vs baseline: 4.1108x; 1.0859x over previous
#include <cuda_runtime.h>
#include <math.h>
#include <stdint.h>

// Problem constants
#define BB   2
#define SS   2048
#define EE   2048
#define HH   16
#define KVH  4
#define DD   128
#define WINW 512
#define QKVW ((HH + 2*KVH) * DD)   // 3072
#define NROWS (BB * SS)            // 4096

// Scratch (static device globals — allocation-free per harness rules)
__device__ float    g_qkv[(size_t)NROWS * QKVW];        // fp32 qkv (post-RoPE)
__device__ uint32_t g_attn[(size_t)NROWS * HH * DD];    // tf32 bits of attn out
__device__ uint32_t g_x32[(size_t)NROWS * EE];          // tf32 bits of x [M][K]
__device__ uint32_t g_wqkvT[(size_t)QKVW * EE];         // tf32 w_qkv^T [N=3072][K=2048]
__device__ uint32_t g_woT[(size_t)EE * EE];             // tf32 w_o^T   [N=2048][K=2048]

__device__ __forceinline__ uint32_t f2tf(float x) {
    uint32_t r;
    asm volatile("cvt.rna.tf32.f32 %0, %1;" : "=r"(r) : "f"(x));
    return r;
}

__device__ __forceinline__ void mma_tf32(float* c, const uint32_t* a, const uint32_t* b) {
    asm volatile(
        "mma.sync.aligned.m16n8k8.row.col.f32.tf32.tf32.f32 "
        "{%0,%1,%2,%3}, {%4,%5,%6,%7}, {%8,%9}, {%0,%1,%2,%3};\n"
        : "+f"(c[0]), "+f"(c[1]), "+f"(c[2]), "+f"(c[3])
        : "r"(a[0]), "r"(a[1]), "r"(a[2]), "r"(a[3]), "r"(b[0]), "r"(b[1]));
}

__device__ __forceinline__ void ldsm4(uint32_t* d, uint32_t a) {
    asm volatile("ldmatrix.sync.aligned.m8n8.x4.shared.b16 {%0,%1,%2,%3}, [%4];"
        : "=r"(d[0]), "=r"(d[1]), "=r"(d[2]), "=r"(d[3]) : "r"(a));
}

__device__ __forceinline__ void cp_async_16(uint32_t smem_addr, const void* gptr) {
    asm volatile("cp.async.cg.shared.global [%0], [%1], 16;" :: "r"(smem_addr), "l"(gptr));
}

#define SW128(b) ((b) ^ ((((uint32_t)(b)) >> 3) & 0x70))

// ---------------------------------------------------------------------------
// Prep kernels
// ---------------------------------------------------------------------------
__global__ void cvt_tf32_kernel(const float* __restrict__ in, uint32_t* __restrict__ outp, int n4)
{
    int i = blockIdx.x * blockDim.x + threadIdx.x;
    if (i < n4) {
        float4 v = ((const float4*)in)[i];
        uint4 u;
        u.x = f2tf(v.x); u.y = f2tf(v.y); u.z = f2tf(v.z); u.w = f2tf(v.w);
        ((uint4*)outp)[i] = u;
    }
}

// in [R][C] fp32 -> out [C][R] tf32 bits
__global__ void transpose_cvt_kernel(const float* __restrict__ in, uint32_t* __restrict__ outp,
                                     int R, int C)
{
    __shared__ uint32_t t[32][33];
    const int bx = blockIdx.x * 32;   // col base (C)
    const int by = blockIdx.y * 32;   // row base (R)
    #pragma unroll
    for (int j = 0; j < 4; j++)
        t[threadIdx.y + j * 8][threadIdx.x] =
            f2tf(in[(size_t)(by + threadIdx.y + j * 8) * C + bx + threadIdx.x]);
    __syncthreads();
    #pragma unroll
    for (int j = 0; j < 4; j++)
        outp[(size_t)(bx + threadIdx.y + j * 8) * R + by + threadIdx.x] =
            t[threadIdx.x][threadIdx.y + j * 8];
}

// ---------------------------------------------------------------------------
// TF32 mma.sync GEMM v3: C[M,N] = A[M,K] * Bt[N,K]^T
// A: tf32 bits [M][K]; Bt: tf32 bits [N][K] (pre-transposed weights).
// CTA tile 256x128, 8 warps (4m x 2n), warp tile 64x64, BK=32.
// Both operands K-major in smem, SW128 128-byte rows, ldmatrix.x4 fragments.
// 3-stage cp.async pipeline.
// ---------------------------------------------------------------------------
#define AST_BYTES 32768u           // 256 rows x 128 B
#define BST_BYTES 16384u           // 128 rows x 128 B
#define STG_BYTES 49152u
#define NSTAGE    3
#define GEMM_SMEM (NSTAGE * STG_BYTES)   // 147456

__global__ void __launch_bounds__(256) gemm_tf32_v3(
    const uint32_t* __restrict__ A, const uint32_t* __restrict__ Bt,
    float* __restrict__ C, int M, int N, int K)
{
    extern __shared__ uint32_t smu[];
    uint32_t smem_base;
    asm("{ .reg .u64 t; cvta.to.shared.u64 t, %1; cvt.u32.u64 %0, t; }"
        : "=r"(smem_base) : "l"(smu));

    const int tid    = threadIdx.x;
    const int warp   = tid >> 5;
    const int lane   = tid & 31;
    const int g      = lane >> 2;
    const int l4     = lane & 3;
    const int r      = lane & 7;     // ldmatrix row within matrix
    const int q      = lane >> 3;    // ldmatrix matrix selector
    const int warp_m = warp >> 1;    // 0..3
    const int warp_n = warp & 1;     // 0..1
    const int bm     = blockIdx.y * 256;
    const int bn     = blockIdx.x * 128;

    // loaders
    const int ld_row = tid >> 3;          // A: 0..255 (with i), B: 0..127
    const int ld_ch  = tid & 7;           // 16B chunk
    const uint32_t xr = (uint32_t)r << 4; // swizzle XOR term (row&7)<<4

    // fragment lane-relative tile offsets (bytes)
    uint32_t relA[4], relB[4];
    #pragma unroll
    for (int mt = 0; mt < 4; mt++)
        relA[mt] = (uint32_t)(warp_m * 64 + mt * 16 + r + (q & 1) * 8) * 128;
    #pragma unroll
    for (int p = 0; p < 4; p++)
        relB[p] = (uint32_t)(warp_n * 64 + p * 16 + r + (q >> 1) * 8) * 128;
    const uint32_t colA = (uint32_t)(q >> 1) * 16;
    const uint32_t colB = (uint32_t)(q & 1) * 16;

    const int ntiles = K / 32;

    auto issue_stage = [&](int s) {
        const uint32_t stgA = smem_base + (uint32_t)(s % NSTAGE) * STG_BYTES;
        const uint32_t stgB = stgA + AST_BYTES;
        const int k0 = s * 32;
        #pragma unroll
        for (int i = 0; i < 8; i++) {
            const int idx = tid + i * 256;
            const int row = idx >> 3;
            const int ch  = idx & 7;
            const uint32_t byte = (uint32_t)row * 128 + (uint32_t)ch * 16;
            cp_async_16(stgA + SW128(byte), &A[(size_t)(bm + row) * K + k0 + ch * 4]);
        }
        #pragma unroll
        for (int i = 0; i < 4; i++) {
            const int idx = tid + i * 256;
            const int row = idx >> 3;
            const int ch  = idx & 7;
            const uint32_t byte = (uint32_t)row * 128 + (uint32_t)ch * 16;
            cp_async_16(stgB + SW128(byte), &Bt[(size_t)(bn + row) * K + k0 + ch * 4]);
        }
        asm volatile("cp.async.commit_group;" ::: "memory");
    };

    float acc[4][8][4];
    #pragma unroll
    for (int mt = 0; mt < 4; mt++)
        #pragma unroll
        for (int nt = 0; nt < 8; nt++)
            #pragma unroll
            for (int i = 0; i < 4; i++) acc[mt][nt][i] = 0.f;

    issue_stage(0);
    issue_stage(1);

    for (int it = 0; it < ntiles; it++) {
        if (it + 1 < ntiles)
            asm volatile("cp.async.wait_group 1;" ::: "memory");
        else
            asm volatile("cp.async.wait_group 0;" ::: "memory");
        __syncthreads();

        if (it + 2 < ntiles) issue_stage(it + 2);

        const uint32_t stgA = smem_base + (uint32_t)(it % NSTAGE) * STG_BYTES;
        const uint32_t stgB = stgA + AST_BYTES;

        #pragma unroll
        for (int kk = 0; kk < 4; kk++) {
            const uint32_t offA = ((uint32_t)kk * 32 + colA) ^ xr;
            const uint32_t offB = ((uint32_t)kk * 32 + colB) ^ xr;
            uint32_t af[4][4], bf[8][2];
            #pragma unroll
            for (int mt = 0; mt < 4; mt++)
                ldsm4(af[mt], stgA + relA[mt] + offA);
            #pragma unroll
            for (int p = 0; p < 4; p++) {
                uint32_t bq[4];
                ldsm4(bq, stgB + relB[p] + offB);
                bf[2 * p][0]     = bq[0];
                bf[2 * p][1]     = bq[1];
                bf[2 * p + 1][0] = bq[2];
                bf[2 * p + 1][1] = bq[3];
            }
            #pragma unroll
            for (int mt = 0; mt < 4; mt++)
                #pragma unroll
                for (int nt = 0; nt < 8; nt++)
                    mma_tf32(acc[mt][nt], af[mt], bf[nt]);
        }
        __syncthreads();
    }

    // epilogue
    #pragma unroll
    for (int mt = 0; mt < 4; mt++) {
        const int row0 = bm + warp_m * 64 + mt * 16 + g;
        #pragma unroll
        for (int nt = 0; nt < 8; nt++) {
            const int col = bn + warp_n * 64 + nt * 8 + 2 * l4;
            *(float2*)&C[(size_t)row0 * N + col] =
                make_float2(acc[mt][nt][0], acc[mt][nt][1]);
            *(float2*)&C[(size_t)(row0 + 8) * N + col] =
                make_float2(acc[mt][nt][2], acc[mt][nt][3]);
        }
    }
}

// ---------------------------------------------------------------------------
// RoPE in-place on q,k slices of g_qkv.
// ---------------------------------------------------------------------------
__global__ void rope_kernel(float* __restrict__ qkv)
{
    const int bs   = blockIdx.x;
    const int head = blockIdx.y;
    const int d    = threadIdx.x;
    const int s    = bs & (SS - 1);

    float* base = qkv + (size_t)bs * QKVW +
                  (head < HH ? head * DD : HH * DD + (head - HH) * DD);

    const float inv_freq = exp2f(-(float)d * 0.311430758895690262f);
    const float ang = (float)s * inv_freq;
    float sn, cs;
    sincosf(ang, &sn, &cs);

    const float x0 = base[d];
    const float x1 = base[d + 64];
    base[d]      = x0 * cs - x1 * sn;
    base[d + 64] = x1 * cs + x0 * sn;
}

// ---------------------------------------------------------------------------
// TF32 mma.sync flash attention (validated round 3). Output = tf32 bits.
// ---------------------------------------------------------------------------
#define BQ 128
#define KT 64
#define KSTR 132
#define VSTR 136
#define MASKVAL -3.0e38f

__global__ void __launch_bounds__(256) attn_tc_kernel(
    const float* __restrict__ qkv, uint32_t* __restrict__ out)
{
    extern __shared__ uint32_t smem[];
    uint32_t* Ks = smem;
    uint32_t* Vs = smem + 64 * KSTR;

    const int tid  = threadIdx.x;
    const int warp = tid >> 5;
    const int lane = tid & 31;
    const int g    = lane >> 2;
    const int l4   = lane & 3;
    const int b    = blockIdx.z;
    const int h    = blockIdx.y;
    const int q0   = blockIdx.x * BQ;
    const int gkv  = h >> 2;
    const float scale = 0.088388347648318447f;

    uint32_t qf[16][4];
    #pragma unroll
    for (int pass = 0; pass < 2; pass++) {
        for (int idx = tid; idx < 64 * 32; idx += 256) {
            int rr = idx >> 5, c4 = (idx & 31) << 2;
            float4 v = *(const float4*)&qkv[(size_t)(b * SS + q0 + pass * 64 + rr) * QKVW
                                            + h * DD + c4];
            uint4 u;
            u.x = f2tf(v.x * scale); u.y = f2tf(v.y * scale);
            u.z = f2tf(v.z * scale); u.w = f2tf(v.w * scale);
            *(uint4*)&Ks[rr * KSTR + c4] = u;
        }
        __syncthreads();
        if ((warp >> 2) == pass) {
            const int lr = (warp & 3) * 16;
            #pragma unroll
            for (int k = 0; k < 16; k++) {
                qf[k][0] = Ks[(lr + g)     * KSTR + k * 8 + l4];
                qf[k][1] = Ks[(lr + g + 8) * KSTR + k * 8 + l4];
                qf[k][2] = Ks[(lr + g)     * KSTR + k * 8 + l4 + 4];
                qf[k][3] = Ks[(lr + g + 8) * KSTR + k * 8 + l4 + 4];
            }
        }
        __syncthreads();
    }

    float o[16][4];
    #pragma unroll
    for (int dt = 0; dt < 16; dt++)
        #pragma unroll
        for (int i = 0; i < 4; i++) o[dt][i] = 0.f;
    float m_a = -1e30f, m_b = -1e30f, l_a = 0.f, l_b = 0.f;

    const int i_lo = q0 + warp * 16;
    const int i_a  = i_lo + g;
    const int i_b  = i_a + 8;
    const int js   = max(0, q0 - WINW);

    for (int kt0 = js; kt0 < q0 + BQ; kt0 += KT) {
        for (int idx = tid; idx < 64 * 32; idx += 256) {
            int rr = idx >> 5, c4 = (idx & 31) << 2;
            size_t rowbase = (size_t)(b * SS + kt0 + rr) * QKVW + HH * DD + gkv * DD;
            float4 kv = *(const float4*)&qkv[rowbase + c4];
            uint4 uk;
            uk.x = f2tf(kv.x); uk.y = f2tf(kv.y); uk.z = f2tf(kv.z); uk.w = f2tf(kv.w);
            *(uint4*)&Ks[rr * KSTR + c4] = uk;
            float4 vv = *(const float4*)&qkv[rowbase + KVH * DD + c4];
            uint4 uv;
            uv.x = f2tf(vv.x); uv.y = f2tf(vv.y); uv.z = f2tf(vv.z); uv.w = f2tf(vv.w);
            *(uint4*)&Vs[rr * VSTR + c4] = uv;
        }
        __syncthreads();

        float s[8][4];
        #pragma unroll
        for (int nt = 0; nt < 8; nt++)
            #pragma unroll
            for (int i = 0; i < 4; i++) s[nt][i] = 0.f;

        #pragma unroll
        for (int k = 0; k < 16; k++) {
            #pragma unroll
            for (int nt = 0; nt < 8; nt++) {
                uint32_t bfr[2];
                bfr[0] = Ks[(nt * 8 + g) * KSTR + k * 8 + l4];
                bfr[1] = Ks[(nt * 8 + g) * KSTR + k * 8 + l4 + 4];
                mma_tf32(s[nt], qf[k], bfr);
            }
        }

        #pragma unroll
        for (int nt = 0; nt < 8; nt++) {
            const int j0 = kt0 + nt * 8;
            const bool allvalid = (j0 + 7 <= i_lo) && (i_lo + 15 - j0 < WINW);
            if (!allvalid) {
                const int ja = j0 + 2 * l4, jb = ja + 1;
                if (!(ja <= i_a && i_a - ja < WINW)) s[nt][0] = MASKVAL;
                if (!(jb <= i_a && i_a - jb < WINW)) s[nt][1] = MASKVAL;
                if (!(ja <= i_b && i_b - ja < WINW)) s[nt][2] = MASKVAL;
                if (!(jb <= i_b && i_b - jb < WINW)) s[nt][3] = MASKVAL;
            }
        }

        float ta = MASKVAL, tb = MASKVAL;
        #pragma unroll
        for (int nt = 0; nt < 8; nt++) {
            ta = fmaxf(ta, fmaxf(s[nt][0], s[nt][1]));
            tb = fmaxf(tb, fmaxf(s[nt][2], s[nt][3]));
        }
        ta = fmaxf(ta, __shfl_xor_sync(0xffffffffu, ta, 1));
        ta = fmaxf(ta, __shfl_xor_sync(0xffffffffu, ta, 2));
        tb = fmaxf(tb, __shfl_xor_sync(0xffffffffu, tb, 1));
        tb = fmaxf(tb, __shfl_xor_sync(0xffffffffu, tb, 2));

        const float mna = fmaxf(m_a, ta);
        const float mnb = fmaxf(m_b, tb);
        const float alpha_a = __expf(m_a - mna);
        const float alpha_b = __expf(m_b - mnb);
        m_a = mna; m_b = mnb;

        float ra = 0.f, rb = 0.f;
        #pragma unroll
        for (int nt = 0; nt < 8; nt++) {
            s[nt][0] = __expf(s[nt][0] - m_a);
            s[nt][1] = __expf(s[nt][1] - m_a);
            s[nt][2] = __expf(s[nt][2] - m_b);
            s[nt][3] = __expf(s[nt][3] - m_b);
            ra += s[nt][0] + s[nt][1];
            rb += s[nt][2] + s[nt][3];
        }
        ra += __shfl_xor_sync(0xffffffffu, ra, 1);
        ra += __shfl_xor_sync(0xffffffffu, ra, 2);
        rb += __shfl_xor_sync(0xffffffffu, rb, 1);
        rb += __shfl_xor_sync(0xffffffffu, rb, 2);
        l_a = l_a * alpha_a + ra;
        l_b = l_b * alpha_b + rb;

        #pragma unroll
        for (int dt = 0; dt < 16; dt++) {
            o[dt][0] *= alpha_a; o[dt][1] *= alpha_a;
            o[dt][2] *= alpha_b; o[dt][3] *= alpha_b;
        }

        const int src0 = (lane & ~3) | (l4 >> 1);
        const int src1 = src0 + 2;
        const bool odd = (l4 & 1);
        #pragma unroll
        for (int nt = 0; nt < 8; nt++) {
            float u0 = __shfl_sync(0xffffffffu, s[nt][0], src0);
            float u1 = __shfl_sync(0xffffffffu, s[nt][1], src0);
            float w0 = __shfl_sync(0xffffffffu, s[nt][0], src1);
            float w1 = __shfl_sync(0xffffffffu, s[nt][1], src1);
            float x0 = __shfl_sync(0xffffffffu, s[nt][2], src0);
            float x1 = __shfl_sync(0xffffffffu, s[nt][3], src0);
            float y0 = __shfl_sync(0xffffffffu, s[nt][2], src1);
            float y1 = __shfl_sync(0xffffffffu, s[nt][3], src1);
            uint32_t ap[4];
            ap[0] = f2tf(odd ? u1 : u0);
            ap[1] = f2tf(odd ? x1 : x0);
            ap[2] = f2tf(odd ? w1 : w0);
            ap[3] = f2tf(odd ? y1 : y0);
            #pragma unroll
            for (int dt = 0; dt < 16; dt++) {
                uint32_t bfr[2];
                bfr[0] = Vs[(nt * 8 + l4)     * VSTR + dt * 8 + g];
                bfr[1] = Vs[(nt * 8 + l4 + 4) * VSTR + dt * 8 + g];
                mma_tf32(o[dt], ap, bfr);
            }
        }
        __syncthreads();
    }

    const float inv_a = 1.0f / l_a;
    const float inv_b = 1.0f / l_b;
    #pragma unroll
    for (int dt = 0; dt < 16; dt++) {
        const int col = h * DD + dt * 8 + 2 * l4;
        *(uint2*)&out[(size_t)(b * SS + i_a) * (HH * DD) + col] =
            make_uint2(f2tf(o[dt][0] * inv_a), f2tf(o[dt][1] * inv_a));
        *(uint2*)&out[(size_t)(b * SS + i_b) * (HH * DD) + col] =
            make_uint2(f2tf(o[dt][2] * inv_b), f2tf(o[dt][3] * inv_b));
    }
}

// ---------------------------------------------------------------------------
extern "C" void kernel_launch(void* const* d_in, const int* in_sizes, int n_in,
                              void* d_out, int out_size)
{
    const float* x     = (const float*)d_in[0];
    const float* w_qkv = (const float*)d_in[1];
    const float* w_o   = (const float*)d_in[2];
    float* out = (float*)d_out;

    float*    qkv_ptr  = nullptr;
    uint32_t* attn_ptr = nullptr;
    uint32_t* x32_ptr  = nullptr;
    uint32_t* wqkvT    = nullptr;
    uint32_t* woT      = nullptr;
    cudaGetSymbolAddress((void**)&qkv_ptr,  g_qkv);
    cudaGetSymbolAddress((void**)&attn_ptr, g_attn);
    cudaGetSymbolAddress((void**)&x32_ptr,  g_x32);
    cudaGetSymbolAddress((void**)&wqkvT,    g_wqkvT);
    cudaGetSymbolAddress((void**)&woT,      g_woT);

    cudaFuncSetAttribute(gemm_tf32_v3,
                         cudaFuncAttributeMaxDynamicSharedMemorySize, GEMM_SMEM);
    const int ATTN_SMEM = (64 * KSTR + 64 * VSTR) * (int)sizeof(uint32_t);
    cudaFuncSetAttribute(attn_tc_kernel,
                         cudaFuncAttributeMaxDynamicSharedMemorySize, ATTN_SMEM);

    // 0) prep: x -> tf32; weights -> transposed tf32 [N][K]
    {
        int n4 = (NROWS * EE) / 4;
        cvt_tf32_kernel<<<(n4 + 255) / 256, 256>>>(x, x32_ptr, n4);
        dim3 blk(32, 8);
        transpose_cvt_kernel<<<dim3(QKVW / 32, EE / 32), blk>>>(w_qkv, wqkvT, EE, QKVW);
        transpose_cvt_kernel<<<dim3(EE / 32, EE / 32), blk>>>(w_o, woT, EE, EE);
    }
    // 1) QKV projection: [4096,2048] @ [2048,3072]
    {
        dim3 grid(QKVW / 128, NROWS / 256);
        gemm_tf32_v3<<<grid, 256, GEMM_SMEM>>>(x32_ptr, wqkvT, qkv_ptr, NROWS, QKVW, EE);
    }
    // 2) RoPE
    {
        dim3 grid(NROWS, HH + KVH);
        rope_kernel<<<grid, 64>>>(qkv_ptr);
    }
    // 3) Flash attention (writes tf32 bits)
    {
        dim3 grid(SS / BQ, HH, BB);
        attn_tc_kernel<<<grid, 256, ATTN_SMEM>>>(qkv_ptr, attn_ptr);
    }
    // 4) Output projection: [4096,2048] @ [2048,2048]
    {
        dim3 grid(EE / 128, NROWS / 256);
        gemm_tf32_v3<<<grid, 256, GEMM_SMEM>>>(attn_ptr, woT, out, NROWS, EE, EE);
    }
}

// round 7
// speedup vs baseline: 4.2333x; 1.0298x over previous
#include <cuda_runtime.h>
#include <math.h>
#include <stdint.h>

// Problem constants
#define BB   2
#define SS   2048
#define EE   2048
#define HH   16
#define KVH  4
#define DD   128
#define WINW 512
#define QKVW ((HH + 2*KVH) * DD)   // 3072
#define NROWS (BB * SS)            // 4096

// Scratch (static device globals)
__device__ float    g_qkv[(size_t)NROWS * QKVW];        // fp32 qkv (pre-RoPE)
__device__ uint32_t g_attn[(size_t)NROWS * HH * DD];    // tf32 bits of attn out
__device__ uint32_t g_x32[(size_t)NROWS * EE];          // tf32 bits of x [M][K]
__device__ uint32_t g_wqkvT[(size_t)QKVW * EE];         // tf32 w_qkv^T [N][K]
__device__ uint32_t g_woT[(size_t)EE * EE];             // tf32 w_o^T   [N][K]
__device__ uint32_t g_q32[(size_t)NROWS * HH * DD];     // roped+scaled Q tf32
__device__ uint32_t g_k32[(size_t)NROWS * KVH * DD];    // roped K tf32
__device__ uint32_t g_v32[(size_t)NROWS * KVH * DD];    // V tf32

__device__ __forceinline__ uint32_t f2tf(float x) {
    uint32_t r;
    asm volatile("cvt.rna.tf32.f32 %0, %1;" : "=r"(r) : "f"(x));
    return r;
}

__device__ __forceinline__ void mma_tf32(float* c, const uint32_t* a, const uint32_t* b) {
    asm volatile(
        "mma.sync.aligned.m16n8k8.row.col.f32.tf32.tf32.f32 "
        "{%0,%1,%2,%3}, {%4,%5,%6,%7}, {%8,%9}, {%0,%1,%2,%3};\n"
        : "+f"(c[0]), "+f"(c[1]), "+f"(c[2]), "+f"(c[3])
        : "r"(a[0]), "r"(a[1]), "r"(a[2]), "r"(a[3]), "r"(b[0]), "r"(b[1]));
}

__device__ __forceinline__ void ldsm4(uint32_t* d, uint32_t a) {
    asm volatile("ldmatrix.sync.aligned.m8n8.x4.shared.b16 {%0,%1,%2,%3}, [%4];"
        : "=r"(d[0]), "=r"(d[1]), "=r"(d[2]), "=r"(d[3]) : "r"(a));
}

__device__ __forceinline__ void cp_async_16(uint32_t smem_addr, const void* gptr) {
    asm volatile("cp.async.cg.shared.global [%0], [%1], 16;" :: "r"(smem_addr), "l"(gptr));
}

#define CP_COMMIT()  asm volatile("cp.async.commit_group;" ::: "memory")
#define CP_WAIT(n)   asm volatile("cp.async.wait_group %0;" :: "n"(n) : "memory")

#define SW128(b) ((b) ^ ((((uint32_t)(b)) >> 3) & 0x70))

// ---------------------------------------------------------------------------
// Prep kernels
// ---------------------------------------------------------------------------
__global__ void cvt_tf32_kernel(const float* __restrict__ in, uint32_t* __restrict__ outp, int n4)
{
    int i = blockIdx.x * blockDim.x + threadIdx.x;
    if (i < n4) {
        float4 v = ((const float4*)in)[i];
        uint4 u;
        u.x = f2tf(v.x); u.y = f2tf(v.y); u.z = f2tf(v.z); u.w = f2tf(v.w);
        ((uint4*)outp)[i] = u;
    }
}

// in [R][C] fp32 -> out [C][R] tf32 bits
__global__ void transpose_cvt_kernel(const float* __restrict__ in, uint32_t* __restrict__ outp,
                                     int R, int C)
{
    __shared__ uint32_t t[32][33];
    const int bx = blockIdx.x * 32;
    const int by = blockIdx.y * 32;
    #pragma unroll
    for (int j = 0; j < 4; j++)
        t[threadIdx.y + j * 8][threadIdx.x] =
            f2tf(in[(size_t)(by + threadIdx.y + j * 8) * C + bx + threadIdx.x]);
    __syncthreads();
    #pragma unroll
    for (int j = 0; j < 4; j++)
        outp[(size_t)(bx + threadIdx.y + j * 8) * R + by + threadIdx.x] =
            t[threadIdx.x][threadIdx.y + j * 8];
}

// ---------------------------------------------------------------------------
// RoPE v2: fused rope + tf32 convert. One block per (b,s) row; cos/sin table
// computed once per block (64 entries).  q -> g_q32 (scale folded),
// k -> g_k32, v -> g_v32.
// ---------------------------------------------------------------------------
__global__ void __launch_bounds__(256) rope_cvt_kernel(
    const float* __restrict__ qkv,
    uint32_t* __restrict__ q32, uint32_t* __restrict__ k32, uint32_t* __restrict__ v32)
{
    __shared__ float cs[64], sn[64];
    const int bs = blockIdx.x;
    const int t  = threadIdx.x;
    const int s  = bs & (SS - 1);

    if (t < 64) {
        const float inv_freq = exp2f(-(float)t * 0.311430758895690262f);
        sincosf((float)s * inv_freq, &sn[t], &cs[t]);
    }
    __syncthreads();

    const float* row = qkv + (size_t)bs * QKVW;
    const float scale = 0.088388347648318447f;  // 1/sqrt(128)

    // q + k heads: 20 heads x 64 pairs
    for (int p = t; p < (HH + KVH) * 64; p += 256) {
        const int head = p >> 6;
        const int d    = p & 63;
        const float* base = row + (head < HH ? head * DD : HH * DD + (head - HH) * DD);
        const float x0 = base[d];
        const float x1 = base[d + 64];
        const float r0 = x0 * cs[d] - x1 * sn[d];
        const float r1 = x1 * cs[d] + x0 * sn[d];
        if (head < HH) {
            uint32_t* dst = q32 + (size_t)bs * (HH * DD) + head * DD;
            dst[d]      = f2tf(r0 * scale);
            dst[d + 64] = f2tf(r1 * scale);
        } else {
            uint32_t* dst = k32 + (size_t)bs * (KVH * DD) + (head - HH) * DD;
            dst[d]      = f2tf(r0);
            dst[d + 64] = f2tf(r1);
        }
    }
    // v: plain convert
    for (int i = t; i < KVH * DD; i += 256)
        v32[(size_t)bs * (KVH * DD) + i] = f2tf(row[(HH + KVH) * DD + i]);
}

// ---------------------------------------------------------------------------
// TF32 mma.sync GEMM v4: C[M,N] = A[M,K] * Bt[N,K]^T
// v3 + single sync per k-tile + fragment double-buffering across k8 steps.
// CTA 256x128, 8 warps (4m x 2n), warp tile 64x64, BK=32, 3-stage cp.async.
// ---------------------------------------------------------------------------
#define AST_BYTES 32768u
#define BST_BYTES 16384u
#define STG_BYTES 49152u
#define NSTAGE    3
#define GEMM_SMEM (NSTAGE * STG_BYTES)

__global__ void __launch_bounds__(256) gemm_tf32_v4(
    const uint32_t* __restrict__ A, const uint32_t* __restrict__ Bt,
    float* __restrict__ C, int M, int N, int K)
{
    extern __shared__ uint32_t smu[];
    uint32_t smem_base;
    asm("{ .reg .u64 t; cvta.to.shared.u64 t, %1; cvt.u32.u64 %0, t; }"
        : "=r"(smem_base) : "l"(smu));

    const int tid    = threadIdx.x;
    const int warp   = tid >> 5;
    const int lane   = tid & 31;
    const int g      = lane >> 2;
    const int l4     = lane & 3;
    const int r      = lane & 7;
    const int q      = lane >> 3;
    const int warp_m = warp >> 1;
    const int warp_n = warp & 1;
    const int bm     = blockIdx.y * 256;
    const int bn     = blockIdx.x * 128;

    const uint32_t xr = (uint32_t)r << 4;

    uint32_t relA[4], relB[4];
    #pragma unroll
    for (int mt = 0; mt < 4; mt++)
        relA[mt] = (uint32_t)(warp_m * 64 + mt * 16 + r + (q & 1) * 8) * 128;
    #pragma unroll
    for (int p = 0; p < 4; p++)
        relB[p] = (uint32_t)(warp_n * 64 + p * 16 + r + (q >> 1) * 8) * 128;
    const uint32_t colA = (uint32_t)(q >> 1) * 16;
    const uint32_t colB = (uint32_t)(q & 1) * 16;

    const int ntiles = K / 32;

    auto issue_stage = [&](int s) {
        const uint32_t stgA = smem_base + (uint32_t)(s % NSTAGE) * STG_BYTES;
        const uint32_t stgB = stgA + AST_BYTES;
        const int k0 = s * 32;
        #pragma unroll
        for (int i = 0; i < 8; i++) {
            const int idx = tid + i * 256;
            const int row = idx >> 3;
            const int ch  = idx & 7;
            const uint32_t byte = (uint32_t)row * 128 + (uint32_t)ch * 16;
            cp_async_16(stgA + SW128(byte), &A[(size_t)(bm + row) * K + k0 + ch * 4]);
        }
        #pragma unroll
        for (int i = 0; i < 4; i++) {
            const int idx = tid + i * 256;
            const int row = idx >> 3;
            const int ch  = idx & 7;
            const uint32_t byte = (uint32_t)row * 128 + (uint32_t)ch * 16;
            cp_async_16(stgB + SW128(byte), &Bt[(size_t)(bn + row) * K + k0 + ch * 4]);
        }
        CP_COMMIT();
    };

    float acc[4][8][4];
    #pragma unroll
    for (int mt = 0; mt < 4; mt++)
        #pragma unroll
        for (int nt = 0; nt < 8; nt++)
            #pragma unroll
            for (int i = 0; i < 4; i++) acc[mt][nt][i] = 0.f;

    issue_stage(0);
    issue_stage(1);

    for (int it = 0; it < ntiles; it++) {
        if (it + 1 < ntiles) CP_WAIT(1); else CP_WAIT(0);
        __syncthreads();
        if (it + 2 < ntiles) issue_stage(it + 2);

        const uint32_t stgA = smem_base + (uint32_t)(it % NSTAGE) * STG_BYTES;
        const uint32_t stgB = stgA + AST_BYTES;

        uint32_t af[2][4][4], bf[2][8][2];
        // load kk=0 fragments
        {
            const uint32_t offA = colA ^ xr;
            const uint32_t offB = colB ^ xr;
            #pragma unroll
            for (int mt = 0; mt < 4; mt++) ldsm4(af[0][mt], stgA + relA[mt] + offA);
            #pragma unroll
            for (int p = 0; p < 4; p++) {
                uint32_t bq[4];
                ldsm4(bq, stgB + relB[p] + offB);
                bf[0][2*p][0] = bq[0]; bf[0][2*p][1] = bq[1];
                bf[0][2*p+1][0] = bq[2]; bf[0][2*p+1][1] = bq[3];
            }
        }
        #pragma unroll
        for (int kk = 0; kk < 4; kk++) {
            const int cur = kk & 1;
            if (kk < 3) {
                const int nxt = cur ^ 1;
                const uint32_t offA = ((uint32_t)(kk + 1) * 32 + colA) ^ xr;
                const uint32_t offB = ((uint32_t)(kk + 1) * 32 + colB) ^ xr;
                #pragma unroll
                for (int mt = 0; mt < 4; mt++) ldsm4(af[nxt][mt], stgA + relA[mt] + offA);
                #pragma unroll
                for (int p = 0; p < 4; p++) {
                    uint32_t bq[4];
                    ldsm4(bq, stgB + relB[p] + offB);
                    bf[nxt][2*p][0] = bq[0]; bf[nxt][2*p][1] = bq[1];
                    bf[nxt][2*p+1][0] = bq[2]; bf[nxt][2*p+1][1] = bq[3];
                }
            }
            #pragma unroll
            for (int mt = 0; mt < 4; mt++)
                #pragma unroll
                for (int nt = 0; nt < 8; nt++)
                    mma_tf32(acc[mt][nt], af[cur][mt], bf[cur][nt]);
        }
        // no trailing sync: next iteration's top sync guards buffer reuse
    }

    #pragma unroll
    for (int mt = 0; mt < 4; mt++) {
        const int row0 = bm + warp_m * 64 + mt * 16 + g;
        #pragma unroll
        for (int nt = 0; nt < 8; nt++) {
            const int col = bn + warp_n * 64 + nt * 8 + 2 * l4;
            *(float2*)&C[(size_t)row0 * N + col] =
                make_float2(acc[mt][nt][0], acc[mt][nt][1]);
            *(float2*)&C[(size_t)(row0 + 8) * N + col] =
                make_float2(acc[mt][nt][2], acc[mt][nt][3]);
        }
    }
}

// ---------------------------------------------------------------------------
// Flash attention v2: cp.async double-buffered KV, ldmatrix K fragments.
// CTA = (b, h, 128 queries); 8 warps x 16 query rows; KV tiles of 64.
// K in SW128 layout (4 stacked 64x128B d-blocks); V padded stride 136.
// ---------------------------------------------------------------------------
#define BQ 128
#define MASKVAL -3.0e38f
#define ATT_SMEM 135168   // 2*32768 (K) + 2*34816 (V)

__global__ void __launch_bounds__(256) attn_tc_v2(
    const uint32_t* __restrict__ q32, const uint32_t* __restrict__ k32,
    const uint32_t* __restrict__ v32, uint32_t* __restrict__ out)
{
    extern __shared__ uint32_t smem[];
    uint32_t smb;
    asm("{ .reg .u64 t; cvta.to.shared.u64 t, %1; cvt.u32.u64 %0, t; }"
        : "=r"(smb) : "l"(smem));

    const int tid  = threadIdx.x;
    const int warp = tid >> 5;
    const int lane = tid & 31;
    const int g    = lane >> 2;
    const int l4   = lane & 3;
    const int r    = lane & 7;
    const int qq   = lane >> 3;
    const int b    = blockIdx.z;
    const int h    = blockIdx.y;
    const int q0   = blockIdx.x * BQ;
    const int gkv  = h >> 2;

    const uint32_t kbuf[2] = { 0u, 32768u };
    const uint32_t vbufB[2] = { 65536u, 100352u };   // byte offsets

    // ---- Q staging (padded 132 layout in V buffer 0 region) + frag extraction
    uint32_t* Qs = smem + (vbufB[0] >> 2);
    uint32_t qf[16][4];
    #pragma unroll
    for (int pass = 0; pass < 2; pass++) {
        for (int idx = tid; idx < 64 * 32; idx += 256) {
            const int rr = idx >> 5, c4 = (idx & 31) << 2;
            *(uint4*)&Qs[rr * 132 + c4] =
                *(const uint4*)&q32[(size_t)(b * SS + q0 + pass * 64 + rr) * (HH * DD)
                                    + h * DD + c4];
        }
        __syncthreads();
        if ((warp >> 2) == pass) {
            const int lr = (warp & 3) * 16;
            #pragma unroll
            for (int k = 0; k < 16; k++) {
                qf[k][0] = Qs[(lr + g)     * 132 + k * 8 + l4];
                qf[k][1] = Qs[(lr + g + 8) * 132 + k * 8 + l4];
                qf[k][2] = Qs[(lr + g)     * 132 + k * 8 + l4 + 4];
                qf[k][3] = Qs[(lr + g + 8) * 132 + k * 8 + l4 + 4];
            }
        }
        __syncthreads();
    }

    const int js    = max(0, q0 - WINW);
    const int ntile = (q0 + BQ - js) >> 6;

    // K fragment addressing constants (same scheme as gemm v4 B operand)
    const uint32_t xr = (uint32_t)r << 4;
    uint32_t relK[4];
    #pragma unroll
    for (int p = 0; p < 4; p++)
        relK[p] = (uint32_t)(p * 16 + r + (qq >> 1) * 8) * 128;
    const uint32_t colK = (uint32_t)(qq & 1) * 16;

    auto issue_tile = [&](int t) {
        const int kt0 = js + t * 64;
        const uint32_t kb = smb + kbuf[t & 1];
        const uint32_t vb = smb + vbufB[t & 1];
        #pragma unroll
        for (int i = 0; i < 8; i++) {
            const int idx = tid + i * 256;
            const int key = idx >> 5, c = idx & 31;
            const uint32_t byte = (uint32_t)((c >> 3) * 64 + key) * 128 + (uint32_t)(c & 7) * 16;
            cp_async_16(kb + SW128(byte),
                &k32[((size_t)(b * SS + kt0 + key) * KVH + gkv) * DD + c * 4]);
        }
        #pragma unroll
        for (int i = 0; i < 8; i++) {
            const int idx = tid + i * 256;
            const int key = idx >> 5, c = idx & 31;
            cp_async_16(vb + (uint32_t)(key * 136 + c * 4) * 4,
                &v32[((size_t)(b * SS + kt0 + key) * KVH + gkv) * DD + c * 4]);
        }
        CP_COMMIT();
    };

    float o[16][4];
    #pragma unroll
    for (int dt = 0; dt < 16; dt++)
        #pragma unroll
        for (int i = 0; i < 4; i++) o[dt][i] = 0.f;
    float m_a = -1e30f, m_b = -1e30f, l_a = 0.f, l_b = 0.f;

    const int i_lo = q0 + warp * 16;
    const int i_a  = i_lo + g;
    const int i_b  = i_a + 8;

    issue_tile(0);

    for (int t = 0; t < ntile; t++) {
        CP_WAIT(0);
        __syncthreads();
        if (t + 1 < ntile) issue_tile(t + 1);

        const int kt0 = js + t * 64;
        const uint32_t kb = smb + kbuf[t & 1];
        const uint32_t* Vs = smem + (vbufB[t & 1] >> 2);

        // ---- S = Q K^T (ldmatrix K fragments) ----
        float s[8][4];
        #pragma unroll
        for (int nt = 0; nt < 8; nt++)
            #pragma unroll
            for (int i = 0; i < 4; i++) s[nt][i] = 0.f;

        #pragma unroll
        for (int kk = 0; kk < 16; kk++) {
            const uint32_t rowb = kb + (uint32_t)(kk >> 2) * (64 * 128);
            const uint32_t offK = ((uint32_t)(kk & 3) * 32 + colK) ^ xr;
            uint32_t bf[8][2];
            #pragma unroll
            for (int p = 0; p < 4; p++) {
                uint32_t bq[4];
                ldsm4(bq, rowb + relK[p] + offK);
                bf[2*p][0] = bq[0]; bf[2*p][1] = bq[1];
                bf[2*p+1][0] = bq[2]; bf[2*p+1][1] = bq[3];
            }
            #pragma unroll
            for (int nt = 0; nt < 8; nt++)
                mma_tf32(s[nt], qf[kk], bf[nt]);
        }

        // ---- mask ----
        #pragma unroll
        for (int nt = 0; nt < 8; nt++) {
            const int j0 = kt0 + nt * 8;
            const bool allvalid = (j0 + 7 <= i_lo) && (i_lo + 15 - j0 < WINW);
            if (!allvalid) {
                const int ja = j0 + 2 * l4, jb = ja + 1;
                if (!(ja <= i_a && i_a - ja < WINW)) s[nt][0] = MASKVAL;
                if (!(jb <= i_a && i_a - jb < WINW)) s[nt][1] = MASKVAL;
                if (!(ja <= i_b && i_b - ja < WINW)) s[nt][2] = MASKVAL;
                if (!(jb <= i_b && i_b - jb < WINW)) s[nt][3] = MASKVAL;
            }
        }

        // ---- online softmax ----
        float ta = MASKVAL, tb = MASKVAL;
        #pragma unroll
        for (int nt = 0; nt < 8; nt++) {
            ta = fmaxf(ta, fmaxf(s[nt][0], s[nt][1]));
            tb = fmaxf(tb, fmaxf(s[nt][2], s[nt][3]));
        }
        ta = fmaxf(ta, __shfl_xor_sync(0xffffffffu, ta, 1));
        ta = fmaxf(ta, __shfl_xor_sync(0xffffffffu, ta, 2));
        tb = fmaxf(tb, __shfl_xor_sync(0xffffffffu, tb, 1));
        tb = fmaxf(tb, __shfl_xor_sync(0xffffffffu, tb, 2));

        const float mna = fmaxf(m_a, ta);
        const float mnb = fmaxf(m_b, tb);
        const float alpha_a = __expf(m_a - mna);
        const float alpha_b = __expf(m_b - mnb);
        m_a = mna; m_b = mnb;

        float ra = 0.f, rb = 0.f;
        #pragma unroll
        for (int nt = 0; nt < 8; nt++) {
            s[nt][0] = __expf(s[nt][0] - m_a);
            s[nt][1] = __expf(s[nt][1] - m_a);
            s[nt][2] = __expf(s[nt][2] - m_b);
            s[nt][3] = __expf(s[nt][3] - m_b);
            ra += s[nt][0] + s[nt][1];
            rb += s[nt][2] + s[nt][3];
        }
        ra += __shfl_xor_sync(0xffffffffu, ra, 1);
        ra += __shfl_xor_sync(0xffffffffu, ra, 2);
        rb += __shfl_xor_sync(0xffffffffu, rb, 1);
        rb += __shfl_xor_sync(0xffffffffu, rb, 2);
        l_a = l_a * alpha_a + ra;
        l_b = l_b * alpha_b + rb;

        #pragma unroll
        for (int dt = 0; dt < 16; dt++) {
            o[dt][0] *= alpha_a; o[dt][1] *= alpha_a;
            o[dt][2] *= alpha_b; o[dt][3] *= alpha_b;
        }

        // ---- O += P V ----
        const int src0 = (lane & ~3) | (l4 >> 1);
        const int src1 = src0 + 2;
        const bool odd = (l4 & 1);
        #pragma unroll
        for (int nt = 0; nt < 8; nt++) {
            float u0 = __shfl_sync(0xffffffffu, s[nt][0], src0);
            float u1 = __shfl_sync(0xffffffffu, s[nt][1], src0);
            float w0 = __shfl_sync(0xffffffffu, s[nt][0], src1);
            float w1 = __shfl_sync(0xffffffffu, s[nt][1], src1);
            float x0 = __shfl_sync(0xffffffffu, s[nt][2], src0);
            float x1 = __shfl_sync(0xffffffffu, s[nt][3], src0);
            float y0 = __shfl_sync(0xffffffffu, s[nt][2], src1);
            float y1 = __shfl_sync(0xffffffffu, s[nt][3], src1);
            uint32_t ap[4];
            ap[0] = f2tf(odd ? u1 : u0);
            ap[1] = f2tf(odd ? x1 : x0);
            ap[2] = f2tf(odd ? w1 : w0);
            ap[3] = f2tf(odd ? y1 : y0);
            #pragma unroll
            for (int dt = 0; dt < 16; dt++) {
                uint32_t bfr[2];
                bfr[0] = Vs[(nt * 8 + l4)     * 136 + dt * 8 + g];
                bfr[1] = Vs[(nt * 8 + l4 + 4) * 136 + dt * 8 + g];
                mma_tf32(o[dt], ap, bfr);
            }
        }
        // no trailing sync: next iteration's top sync guards buffer reuse
    }

    const float inv_a = 1.0f / l_a;
    const float inv_b = 1.0f / l_b;
    #pragma unroll
    for (int dt = 0; dt < 16; dt++) {
        const int col = h * DD + dt * 8 + 2 * l4;
        *(uint2*)&out[(size_t)(b * SS + i_a) * (HH * DD) + col] =
            make_uint2(f2tf(o[dt][0] * inv_a), f2tf(o[dt][1] * inv_a));
        *(uint2*)&out[(size_t)(b * SS + i_b) * (HH * DD) + col] =
            make_uint2(f2tf(o[dt][2] * inv_b), f2tf(o[dt][3] * inv_b));
    }
}

// ---------------------------------------------------------------------------
extern "C" void kernel_launch(void* const* d_in, const int* in_sizes, int n_in,
                              void* d_out, int out_size)
{
    const float* x     = (const float*)d_in[0];
    const float* w_qkv = (const float*)d_in[1];
    const float* w_o   = (const float*)d_in[2];
    float* out = (float*)d_out;

    float*    qkv_ptr  = nullptr;
    uint32_t* attn_ptr = nullptr;
    uint32_t* x32_ptr  = nullptr;
    uint32_t* wqkvT    = nullptr;
    uint32_t* woT      = nullptr;
    uint32_t* q32_ptr  = nullptr;
    uint32_t* k32_ptr  = nullptr;
    uint32_t* v32_ptr  = nullptr;
    cudaGetSymbolAddress((void**)&qkv_ptr,  g_qkv);
    cudaGetSymbolAddress((void**)&attn_ptr, g_attn);
    cudaGetSymbolAddress((void**)&x32_ptr,  g_x32);
    cudaGetSymbolAddress((void**)&wqkvT,    g_wqkvT);
    cudaGetSymbolAddress((void**)&woT,      g_woT);
    cudaGetSymbolAddress((void**)&q32_ptr,  g_q32);
    cudaGetSymbolAddress((void**)&k32_ptr,  g_k32);
    cudaGetSymbolAddress((void**)&v32_ptr,  g_v32);

    cudaFuncSetAttribute(gemm_tf32_v4,
                         cudaFuncAttributeMaxDynamicSharedMemorySize, GEMM_SMEM);
    cudaFuncSetAttribute(attn_tc_v2,
                         cudaFuncAttributeMaxDynamicSharedMemorySize, ATT_SMEM);

    // 0) prep: x -> tf32; weights -> transposed tf32 [N][K]
    {
        int n4 = (NROWS * EE) / 4;
        cvt_tf32_kernel<<<(n4 + 255) / 256, 256>>>(x, x32_ptr, n4);
        dim3 blk(32, 8);
        transpose_cvt_kernel<<<dim3(QKVW / 32, EE / 32), blk>>>(w_qkv, wqkvT, EE, QKVW);
        transpose_cvt_kernel<<<dim3(EE / 32, EE / 32), blk>>>(w_o, woT, EE, EE);
    }
    // 1) QKV projection
    {
        dim3 grid(QKVW / 128, NROWS / 256);
        gemm_tf32_v4<<<grid, 256, GEMM_SMEM>>>(x32_ptr, wqkvT, qkv_ptr, NROWS, QKVW, EE);
    }
    // 2) RoPE + tf32 split buffers
    {
        rope_cvt_kernel<<<NROWS, 256>>>(qkv_ptr, q32_ptr, k32_ptr, v32_ptr);
    }
    // 3) Flash attention v2
    {
        dim3 grid(SS / BQ, HH, BB);
        attn_tc_v2<<<grid, 256, ATT_SMEM>>>(q32_ptr, k32_ptr, v32_ptr, attn_ptr);
    }
    // 4) Output projection
    {
        dim3 grid(EE / 128, NROWS / 256);
        gemm_tf32_v4<<<grid, 256, GEMM_SMEM>>>(attn_ptr, woT, out, NROWS, EE, EE);
    }
}

// round 8
// speedup vs baseline: 4.4101x; 1.0418x over previous
#include <cuda_runtime.h>
#include <math.h>
#include <stdint.h>

// Problem constants
#define BB   2
#define SS   2048
#define EE   2048
#define HH   16
#define KVH  4
#define DD   128
#define WINW 512
#define QKVW ((HH + 2*KVH) * DD)   // 3072
#define NROWS (BB * SS)            // 4096

// Scratch (static device globals)
__device__ float    g_qkv[(size_t)NROWS * QKVW];        // fp32 qkv (pre-RoPE)
__device__ uint32_t g_attn[(size_t)NROWS * HH * DD];    // tf32 bits of attn out
__device__ uint32_t g_x32[(size_t)NROWS * EE];          // tf32 bits of x [M][K]
__device__ uint32_t g_wqkvT[(size_t)QKVW * EE];         // tf32 w_qkv^T [N][K]
__device__ uint32_t g_woT[(size_t)EE * EE];             // tf32 w_o^T   [N][K]
__device__ uint32_t g_q32[(size_t)NROWS * HH * DD];     // roped+scaled Q tf32
__device__ uint32_t g_k32[(size_t)NROWS * KVH * DD];    // roped K tf32
__device__ uint32_t g_v32[(size_t)NROWS * KVH * DD];    // V tf32

__device__ __forceinline__ uint32_t f2tf(float x) {
    uint32_t r;
    asm volatile("cvt.rna.tf32.f32 %0, %1;" : "=r"(r) : "f"(x));
    return r;
}

__device__ __forceinline__ void mma_tf32(float* c, const uint32_t* a, const uint32_t* b) {
    asm volatile(
        "mma.sync.aligned.m16n8k8.row.col.f32.tf32.tf32.f32 "
        "{%0,%1,%2,%3}, {%4,%5,%6,%7}, {%8,%9}, {%0,%1,%2,%3};\n"
        : "+f"(c[0]), "+f"(c[1]), "+f"(c[2]), "+f"(c[3])
        : "r"(a[0]), "r"(a[1]), "r"(a[2]), "r"(a[3]), "r"(b[0]), "r"(b[1]));
}

__device__ __forceinline__ void ldsm4(uint32_t* d, uint32_t a) {
    asm volatile("ldmatrix.sync.aligned.m8n8.x4.shared.b16 {%0,%1,%2,%3}, [%4];"
        : "=r"(d[0]), "=r"(d[1]), "=r"(d[2]), "=r"(d[3]) : "r"(a));
}

__device__ __forceinline__ void cp_async_16(uint32_t smem_addr, const void* gptr) {
    asm volatile("cp.async.cg.shared.global [%0], [%1], 16;" :: "r"(smem_addr), "l"(gptr));
}

#define CP_COMMIT()  asm volatile("cp.async.commit_group;" ::: "memory")
#define CP_WAIT(n)   asm volatile("cp.async.wait_group %0;" :: "n"(n) : "memory")

#define SW128(b) ((b) ^ ((((uint32_t)(b)) >> 3) & 0x70))

// ---------------------------------------------------------------------------
// Prep kernels
// ---------------------------------------------------------------------------
__global__ void cvt_tf32_kernel(const float* __restrict__ in, uint32_t* __restrict__ outp, int n4)
{
    int i = blockIdx.x * blockDim.x + threadIdx.x;
    if (i < n4) {
        float4 v = ((const float4*)in)[i];
        uint4 u;
        u.x = f2tf(v.x); u.y = f2tf(v.y); u.z = f2tf(v.z); u.w = f2tf(v.w);
        ((uint4*)outp)[i] = u;
    }
}

// in [R][C] fp32 -> out [C][R] tf32 bits
__global__ void transpose_cvt_kernel(const float* __restrict__ in, uint32_t* __restrict__ outp,
                                     int R, int C)
{
    __shared__ uint32_t t[32][33];
    const int bx = blockIdx.x * 32;
    const int by = blockIdx.y * 32;
    #pragma unroll
    for (int j = 0; j < 4; j++)
        t[threadIdx.y + j * 8][threadIdx.x] =
            f2tf(in[(size_t)(by + threadIdx.y + j * 8) * C + bx + threadIdx.x]);
    __syncthreads();
    #pragma unroll
    for (int j = 0; j < 4; j++)
        outp[(size_t)(bx + threadIdx.y + j * 8) * R + by + threadIdx.x] =
            t[threadIdx.x][threadIdx.y + j * 8];
}

// ---------------------------------------------------------------------------
// RoPE v2: fused rope + tf32 convert (validated round 7).
// ---------------------------------------------------------------------------
__global__ void __launch_bounds__(256) rope_cvt_kernel(
    const float* __restrict__ qkv,
    uint32_t* __restrict__ q32, uint32_t* __restrict__ k32, uint32_t* __restrict__ v32)
{
    __shared__ float cs[64], sn[64];
    const int bs = blockIdx.x;
    const int t  = threadIdx.x;
    const int s  = bs & (SS - 1);

    if (t < 64) {
        const float inv_freq = exp2f(-(float)t * 0.311430758895690262f);
        sincosf((float)s * inv_freq, &sn[t], &cs[t]);
    }
    __syncthreads();

    const float* row = qkv + (size_t)bs * QKVW;
    const float scale = 0.088388347648318447f;  // 1/sqrt(128)

    for (int p = t; p < (HH + KVH) * 64; p += 256) {
        const int head = p >> 6;
        const int d    = p & 63;
        const float* base = row + (head < HH ? head * DD : HH * DD + (head - HH) * DD);
        const float x0 = base[d];
        const float x1 = base[d + 64];
        const float r0 = x0 * cs[d] - x1 * sn[d];
        const float r1 = x1 * cs[d] + x0 * sn[d];
        if (head < HH) {
            uint32_t* dst = q32 + (size_t)bs * (HH * DD) + head * DD;
            dst[d]      = f2tf(r0 * scale);
            dst[d + 64] = f2tf(r1 * scale);
        } else {
            uint32_t* dst = k32 + (size_t)bs * (KVH * DD) + (head - HH) * DD;
            dst[d]      = f2tf(r0);
            dst[d + 64] = f2tf(r1);
        }
    }
    for (int i = t; i < KVH * DD; i += 256)
        v32[(size_t)bs * (KVH * DD) + i] = f2tf(row[(HH + KVH) * DD + i]);
}

// ---------------------------------------------------------------------------
// TF32 mma.sync GEMM v5: v3 mainloop (single-buffered fragments) + single
// sync per k-tile.  C[M,N] = A[M,K] * Bt[N,K]^T.
// CTA 256x128, 8 warps (4m x 2n), warp tile 64x64, BK=32, 3-stage cp.async.
// ---------------------------------------------------------------------------
#define AST_BYTES 32768u
#define BST_BYTES 16384u
#define STG_BYTES 49152u
#define NSTAGE    3
#define GEMM_SMEM (NSTAGE * STG_BYTES)

__global__ void __launch_bounds__(256) gemm_tf32_v5(
    const uint32_t* __restrict__ A, const uint32_t* __restrict__ Bt,
    float* __restrict__ C, int M, int N, int K)
{
    extern __shared__ uint32_t smu[];
    uint32_t smem_base;
    asm("{ .reg .u64 t; cvta.to.shared.u64 t, %1; cvt.u32.u64 %0, t; }"
        : "=r"(smem_base) : "l"(smu));

    const int tid    = threadIdx.x;
    const int warp   = tid >> 5;
    const int lane   = tid & 31;
    const int g      = lane >> 2;
    const int l4     = lane & 3;
    const int r      = lane & 7;
    const int q      = lane >> 3;
    const int warp_m = warp >> 1;
    const int warp_n = warp & 1;
    const int bm     = blockIdx.y * 256;
    const int bn     = blockIdx.x * 128;

    const uint32_t xr = (uint32_t)r << 4;

    uint32_t relA[4], relB[4];
    #pragma unroll
    for (int mt = 0; mt < 4; mt++)
        relA[mt] = (uint32_t)(warp_m * 64 + mt * 16 + r + (q & 1) * 8) * 128;
    #pragma unroll
    for (int p = 0; p < 4; p++)
        relB[p] = (uint32_t)(warp_n * 64 + p * 16 + r + (q >> 1) * 8) * 128;
    const uint32_t colA = (uint32_t)(q >> 1) * 16;
    const uint32_t colB = (uint32_t)(q & 1) * 16;

    const int ntiles = K / 32;

    auto issue_stage = [&](int s) {
        const uint32_t stgA = smem_base + (uint32_t)(s % NSTAGE) * STG_BYTES;
        const uint32_t stgB = stgA + AST_BYTES;
        const int k0 = s * 32;
        #pragma unroll
        for (int i = 0; i < 8; i++) {
            const int idx = tid + i * 256;
            const int row = idx >> 3;
            const int ch  = idx & 7;
            const uint32_t byte = (uint32_t)row * 128 + (uint32_t)ch * 16;
            cp_async_16(stgA + SW128(byte), &A[(size_t)(bm + row) * K + k0 + ch * 4]);
        }
        #pragma unroll
        for (int i = 0; i < 4; i++) {
            const int idx = tid + i * 256;
            const int row = idx >> 3;
            const int ch  = idx & 7;
            const uint32_t byte = (uint32_t)row * 128 + (uint32_t)ch * 16;
            cp_async_16(stgB + SW128(byte), &Bt[(size_t)(bn + row) * K + k0 + ch * 4]);
        }
        CP_COMMIT();
    };

    float acc[4][8][4];
    #pragma unroll
    for (int mt = 0; mt < 4; mt++)
        #pragma unroll
        for (int nt = 0; nt < 8; nt++)
            #pragma unroll
            for (int i = 0; i < 4; i++) acc[mt][nt][i] = 0.f;

    issue_stage(0);
    issue_stage(1);

    for (int it = 0; it < ntiles; it++) {
        if (it + 1 < ntiles) CP_WAIT(1); else CP_WAIT(0);
        __syncthreads();
        if (it + 2 < ntiles) issue_stage(it + 2);

        const uint32_t stgA = smem_base + (uint32_t)(it % NSTAGE) * STG_BYTES;
        const uint32_t stgB = stgA + AST_BYTES;

        #pragma unroll
        for (int kk = 0; kk < 4; kk++) {
            const uint32_t offA = ((uint32_t)kk * 32 + colA) ^ xr;
            const uint32_t offB = ((uint32_t)kk * 32 + colB) ^ xr;
            uint32_t af[4][4], bf[8][2];
            #pragma unroll
            for (int mt = 0; mt < 4; mt++)
                ldsm4(af[mt], stgA + relA[mt] + offA);
            #pragma unroll
            for (int p = 0; p < 4; p++) {
                uint32_t bq[4];
                ldsm4(bq, stgB + relB[p] + offB);
                bf[2 * p][0]     = bq[0];
                bf[2 * p][1]     = bq[1];
                bf[2 * p + 1][0] = bq[2];
                bf[2 * p + 1][1] = bq[3];
            }
            #pragma unroll
            for (int mt = 0; mt < 4; mt++)
                #pragma unroll
                for (int nt = 0; nt < 8; nt++)
                    mma_tf32(acc[mt][nt], af[mt], bf[nt]);
        }
        // single sync per tile: next iteration's top sync guards buffer reuse
    }

    #pragma unroll
    for (int mt = 0; mt < 4; mt++) {
        const int row0 = bm + warp_m * 64 + mt * 16 + g;
        #pragma unroll
        for (int nt = 0; nt < 8; nt++) {
            const int col = bn + warp_n * 64 + nt * 8 + 2 * l4;
            *(float2*)&C[(size_t)row0 * N + col] =
                make_float2(acc[mt][nt][0], acc[mt][nt][1]);
            *(float2*)&C[(size_t)(row0 + 8) * N + col] =
                make_float2(acc[mt][nt][2], acc[mt][nt][3]);
        }
    }
}

// ---------------------------------------------------------------------------
// Flash attention v2 (validated round 7): cp.async double-buffered KV,
// ldmatrix K fragments.
// ---------------------------------------------------------------------------
#define BQ 128
#define MASKVAL -3.0e38f
#define ATT_SMEM 135168

__global__ void __launch_bounds__(256) attn_tc_v2(
    const uint32_t* __restrict__ q32, const uint32_t* __restrict__ k32,
    const uint32_t* __restrict__ v32, uint32_t* __restrict__ out)
{
    extern __shared__ uint32_t smem[];
    uint32_t smb;
    asm("{ .reg .u64 t; cvta.to.shared.u64 t, %1; cvt.u32.u64 %0, t; }"
        : "=r"(smb) : "l"(smem));

    const int tid  = threadIdx.x;
    const int warp = tid >> 5;
    const int lane = tid & 31;
    const int g    = lane >> 2;
    const int l4   = lane & 3;
    const int r    = lane & 7;
    const int qq   = lane >> 3;
    const int b    = blockIdx.z;
    const int h    = blockIdx.y;
    const int q0   = blockIdx.x * BQ;
    const int gkv  = h >> 2;

    const uint32_t kbuf[2] = { 0u, 32768u };
    const uint32_t vbufB[2] = { 65536u, 100352u };

    uint32_t* Qs = smem + (vbufB[0] >> 2);
    uint32_t qf[16][4];
    #pragma unroll
    for (int pass = 0; pass < 2; pass++) {
        for (int idx = tid; idx < 64 * 32; idx += 256) {
            const int rr = idx >> 5, c4 = (idx & 31) << 2;
            *(uint4*)&Qs[rr * 132 + c4] =
                *(const uint4*)&q32[(size_t)(b * SS + q0 + pass * 64 + rr) * (HH * DD)
                                    + h * DD + c4];
        }
        __syncthreads();
        if ((warp >> 2) == pass) {
            const int lr = (warp & 3) * 16;
            #pragma unroll
            for (int k = 0; k < 16; k++) {
                qf[k][0] = Qs[(lr + g)     * 132 + k * 8 + l4];
                qf[k][1] = Qs[(lr + g + 8) * 132 + k * 8 + l4];
                qf[k][2] = Qs[(lr + g)     * 132 + k * 8 + l4 + 4];
                qf[k][3] = Qs[(lr + g + 8) * 132 + k * 8 + l4 + 4];
            }
        }
        __syncthreads();
    }

    const int js    = max(0, q0 - WINW);
    const int ntile = (q0 + BQ - js) >> 6;

    const uint32_t xr = (uint32_t)r << 4;
    uint32_t relK[4];
    #pragma unroll
    for (int p = 0; p < 4; p++)
        relK[p] = (uint32_t)(p * 16 + r + (qq >> 1) * 8) * 128;
    const uint32_t colK = (uint32_t)(qq & 1) * 16;

    auto issue_tile = [&](int t) {
        const int kt0 = js + t * 64;
        const uint32_t kb = smb + kbuf[t & 1];
        const uint32_t vb = smb + vbufB[t & 1];
        #pragma unroll
        for (int i = 0; i < 8; i++) {
            const int idx = tid + i * 256;
            const int key = idx >> 5, c = idx & 31;
            const uint32_t byte = (uint32_t)((c >> 3) * 64 + key) * 128 + (uint32_t)(c & 7) * 16;
            cp_async_16(kb + SW128(byte),
                &k32[((size_t)(b * SS + kt0 + key) * KVH + gkv) * DD + c * 4]);
        }
        #pragma unroll
        for (int i = 0; i < 8; i++) {
            const int idx = tid + i * 256;
            const int key = idx >> 5, c = idx & 31;
            cp_async_16(vb + (uint32_t)(key * 136 + c * 4) * 4,
                &v32[((size_t)(b * SS + kt0 + key) * KVH + gkv) * DD + c * 4]);
        }
        CP_COMMIT();
    };

    float o[16][4];
    #pragma unroll
    for (int dt = 0; dt < 16; dt++)
        #pragma unroll
        for (int i = 0; i < 4; i++) o[dt][i] = 0.f;
    float m_a = -1e30f, m_b = -1e30f, l_a = 0.f, l_b = 0.f;

    const int i_lo = q0 + warp * 16;
    const int i_a  = i_lo + g;
    const int i_b  = i_a + 8;

    issue_tile(0);

    for (int t = 0; t < ntile; t++) {
        CP_WAIT(0);
        __syncthreads();
        if (t + 1 < ntile) issue_tile(t + 1);

        const int kt0 = js + t * 64;
        const uint32_t kb = smb + kbuf[t & 1];
        const uint32_t* Vs = smem + (vbufB[t & 1] >> 2);

        float s[8][4];
        #pragma unroll
        for (int nt = 0; nt < 8; nt++)
            #pragma unroll
            for (int i = 0; i < 4; i++) s[nt][i] = 0.f;

        #pragma unroll
        for (int kk = 0; kk < 16; kk++) {
            const uint32_t rowb = kb + (uint32_t)(kk >> 2) * (64 * 128);
            const uint32_t offK = ((uint32_t)(kk & 3) * 32 + colK) ^ xr;
            uint32_t bf[8][2];
            #pragma unroll
            for (int p = 0; p < 4; p++) {
                uint32_t bq[4];
                ldsm4(bq, rowb + relK[p] + offK);
                bf[2*p][0] = bq[0]; bf[2*p][1] = bq[1];
                bf[2*p+1][0] = bq[2]; bf[2*p+1][1] = bq[3];
            }
            #pragma unroll
            for (int nt = 0; nt < 8; nt++)
                mma_tf32(s[nt], qf[kk], bf[nt]);
        }

        #pragma unroll
        for (int nt = 0; nt < 8; nt++) {
            const int j0 = kt0 + nt * 8;
            const bool allvalid = (j0 + 7 <= i_lo) && (i_lo + 15 - j0 < WINW);
            if (!allvalid) {
                const int ja = j0 + 2 * l4, jb = ja + 1;
                if (!(ja <= i_a && i_a - ja < WINW)) s[nt][0] = MASKVAL;
                if (!(jb <= i_a && i_a - jb < WINW)) s[nt][1] = MASKVAL;
                if (!(ja <= i_b && i_b - ja < WINW)) s[nt][2] = MASKVAL;
                if (!(jb <= i_b && i_b - jb < WINW)) s[nt][3] = MASKVAL;
            }
        }

        float ta = MASKVAL, tb = MASKVAL;
        #pragma unroll
        for (int nt = 0; nt < 8; nt++) {
            ta = fmaxf(ta, fmaxf(s[nt][0], s[nt][1]));
            tb = fmaxf(tb, fmaxf(s[nt][2], s[nt][3]));
        }
        ta = fmaxf(ta, __shfl_xor_sync(0xffffffffu, ta, 1));
        ta = fmaxf(ta, __shfl_xor_sync(0xffffffffu, ta, 2));
        tb = fmaxf(tb, __shfl_xor_sync(0xffffffffu, tb, 1));
        tb = fmaxf(tb, __shfl_xor_sync(0xffffffffu, tb, 2));

        const float mna = fmaxf(m_a, ta);
        const float mnb = fmaxf(m_b, tb);
        const float alpha_a = __expf(m_a - mna);
        const float alpha_b = __expf(m_b - mnb);
        m_a = mna; m_b = mnb;

        float ra = 0.f, rb = 0.f;
        #pragma unroll
        for (int nt = 0; nt < 8; nt++) {
            s[nt][0] = __expf(s[nt][0] - m_a);
            s[nt][1] = __expf(s[nt][1] - m_a);
            s[nt][2] = __expf(s[nt][2] - m_b);
            s[nt][3] = __expf(s[nt][3] - m_b);
            ra += s[nt][0] + s[nt][1];
            rb += s[nt][2] + s[nt][3];
        }
        ra += __shfl_xor_sync(0xffffffffu, ra, 1);
        ra += __shfl_xor_sync(0xffffffffu, ra, 2);
        rb += __shfl_xor_sync(0xffffffffu, rb, 1);
        rb += __shfl_xor_sync(0xffffffffu, rb, 2);
        l_a = l_a * alpha_a + ra;
        l_b = l_b * alpha_b + rb;

        #pragma unroll
        for (int dt = 0; dt < 16; dt++) {
            o[dt][0] *= alpha_a; o[dt][1] *= alpha_a;
            o[dt][2] *= alpha_b; o[dt][3] *= alpha_b;
        }

        const int src0 = (lane & ~3) | (l4 >> 1);
        const int src1 = src0 + 2;
        const bool odd = (l4 & 1);
        #pragma unroll
        for (int nt = 0; nt < 8; nt++) {
            float u0 = __shfl_sync(0xffffffffu, s[nt][0], src0);
            float u1 = __shfl_sync(0xffffffffu, s[nt][1], src0);
            float w0 = __shfl_sync(0xffffffffu, s[nt][0], src1);
            float w1 = __shfl_sync(0xffffffffu, s[nt][1], src1);
            float x0 = __shfl_sync(0xffffffffu, s[nt][2], src0);
            float x1 = __shfl_sync(0xffffffffu, s[nt][3], src0);
            float y0 = __shfl_sync(0xffffffffu, s[nt][2], src1);
            float y1 = __shfl_sync(0xffffffffu, s[nt][3], src1);
            uint32_t ap[4];
            ap[0] = f2tf(odd ? u1 : u0);
            ap[1] = f2tf(odd ? x1 : x0);
            ap[2] = f2tf(odd ? w1 : w0);
            ap[3] = f2tf(odd ? y1 : y0);
            #pragma unroll
            for (int dt = 0; dt < 16; dt++) {
                uint32_t bfr[2];
                bfr[0] = Vs[(nt * 8 + l4)     * 136 + dt * 8 + g];
                bfr[1] = Vs[(nt * 8 + l4 + 4) * 136 + dt * 8 + g];
                mma_tf32(o[dt], ap, bfr);
            }
        }
    }

    const float inv_a = 1.0f / l_a;
    const float inv_b = 1.0f / l_b;
    #pragma unroll
    for (int dt = 0; dt < 16; dt++) {
        const int col = h * DD + dt * 8 + 2 * l4;
        *(uint2*)&out[(size_t)(b * SS + i_a) * (HH * DD) + col] =
            make_uint2(f2tf(o[dt][0] * inv_a), f2tf(o[dt][1] * inv_a));
        *(uint2*)&out[(size_t)(b * SS + i_b) * (HH * DD) + col] =
            make_uint2(f2tf(o[dt][2] * inv_b), f2tf(o[dt][3] * inv_b));
    }
}

// ---------------------------------------------------------------------------
extern "C" void kernel_launch(void* const* d_in, const int* in_sizes, int n_in,
                              void* d_out, int out_size)
{
    const float* x     = (const float*)d_in[0];
    const float* w_qkv = (const float*)d_in[1];
    const float* w_o   = (const float*)d_in[2];
    float* out = (float*)d_out;

    float*    qkv_ptr  = nullptr;
    uint32_t* attn_ptr = nullptr;
    uint32_t* x32_ptr  = nullptr;
    uint32_t* wqkvT    = nullptr;
    uint32_t* woT      = nullptr;
    uint32_t* q32_ptr  = nullptr;
    uint32_t* k32_ptr  = nullptr;
    uint32_t* v32_ptr  = nullptr;
    cudaGetSymbolAddress((void**)&qkv_ptr,  g_qkv);
    cudaGetSymbolAddress((void**)&attn_ptr, g_attn);
    cudaGetSymbolAddress((void**)&x32_ptr,  g_x32);
    cudaGetSymbolAddress((void**)&wqkvT,    g_wqkvT);
    cudaGetSymbolAddress((void**)&woT,      g_woT);
    cudaGetSymbolAddress((void**)&q32_ptr,  g_q32);
    cudaGetSymbolAddress((void**)&k32_ptr,  g_k32);
    cudaGetSymbolAddress((void**)&v32_ptr,  g_v32);

    cudaFuncSetAttribute(gemm_tf32_v5,
                         cudaFuncAttributeMaxDynamicSharedMemorySize, GEMM_SMEM);
    cudaFuncSetAttribute(attn_tc_v2,
                         cudaFuncAttributeMaxDynamicSharedMemorySize, ATT_SMEM);

    // 0) prep: x -> tf32; weights -> transposed tf32 [N][K]
    {
        int n4 = (NROWS * EE) / 4;
        cvt_tf32_kernel<<<(n4 + 255) / 256, 256>>>(x, x32_ptr, n4);
        dim3 blk(32, 8);
        transpose_cvt_kernel<<<dim3(QKVW / 32, EE / 32), blk>>>(w_qkv, wqkvT, EE, QKVW);
        transpose_cvt_kernel<<<dim3(EE / 32, EE / 32), blk>>>(w_o, woT, EE, EE);
    }
    // 1) QKV projection
    {
        dim3 grid(QKVW / 128, NROWS / 256);
        gemm_tf32_v5<<<grid, 256, GEMM_SMEM>>>(x32_ptr, wqkvT, qkv_ptr, NROWS, QKVW, EE);
    }
    // 2) RoPE + tf32 split buffers
    {
        rope_cvt_kernel<<<NROWS, 256>>>(qkv_ptr, q32_ptr, k32_ptr, v32_ptr);
    }
    // 3) Flash attention v2
    {
        dim3 grid(SS / BQ, HH, BB);
        attn_tc_v2<<<grid, 256, ATT_SMEM>>>(q32_ptr, k32_ptr, v32_ptr, attn_ptr);
    }
    // 4) Output projection
    {
        dim3 grid(EE / 128, NROWS / 256);
        gemm_tf32_v5<<<grid, 256, GEMM_SMEM>>>(attn_ptr, woT, out, NROWS, EE, EE);
    }
}

// round 9
// speedup vs baseline: 4.4232x; 1.0030x over previous
#include <cuda_runtime.h>
#include <math.h>
#include <stdint.h>

// Problem constants
#define BB   2
#define SS   2048
#define EE   2048
#define HH   16
#define KVH  4
#define DD   128
#define WINW 512
#define QKVW ((HH + 2*KVH) * DD)   // 3072
#define NROWS (BB * SS)            // 4096

// Scratch (static device globals)
__device__ float    g_qkv[(size_t)NROWS * QKVW];        // fp32 qkv (pre-RoPE)
__device__ uint32_t g_attn[(size_t)NROWS * HH * DD];    // tf32 bits of attn out
__device__ uint32_t g_x32[(size_t)NROWS * EE];          // tf32 bits of x [M][K]
__device__ uint32_t g_wqkvT[(size_t)QKVW * EE];         // tf32 w_qkv^T [N][K]
__device__ uint32_t g_woT[(size_t)EE * EE];             // tf32 w_o^T   [N][K]
__device__ uint32_t g_q32[(size_t)NROWS * HH * DD];     // roped+scaled Q tf32
__device__ uint32_t g_k32[(size_t)NROWS * KVH * DD];    // roped K tf32
__device__ uint32_t g_v32[(size_t)NROWS * KVH * DD];    // V tf32

__device__ __forceinline__ uint32_t f2tf(float x) {
    uint32_t r;
    asm volatile("cvt.rna.tf32.f32 %0, %1;" : "=r"(r) : "f"(x));
    return r;
}

__device__ __forceinline__ void mma_tf32(float* c, const uint32_t* a, const uint32_t* b) {
    asm volatile(
        "mma.sync.aligned.m16n8k8.row.col.f32.tf32.tf32.f32 "
        "{%0,%1,%2,%3}, {%4,%5,%6,%7}, {%8,%9}, {%0,%1,%2,%3};\n"
        : "+f"(c[0]), "+f"(c[1]), "+f"(c[2]), "+f"(c[3])
        : "r"(a[0]), "r"(a[1]), "r"(a[2]), "r"(a[3]), "r"(b[0]), "r"(b[1]));
}

__device__ __forceinline__ void ldsm4(uint32_t* d, uint32_t a) {
    asm volatile("ldmatrix.sync.aligned.m8n8.x4.shared.b16 {%0,%1,%2,%3}, [%4];"
        : "=r"(d[0]), "=r"(d[1]), "=r"(d[2]), "=r"(d[3]) : "r"(a));
}

__device__ __forceinline__ void cp_async_16(uint32_t smem_addr, const void* gptr) {
    asm volatile("cp.async.cg.shared.global [%0], [%1], 16;" :: "r"(smem_addr), "l"(gptr));
}

#define CP_COMMIT()  asm volatile("cp.async.commit_group;" ::: "memory")
#define CP_WAIT(n)   asm volatile("cp.async.wait_group %0;" :: "n"(n) : "memory")

#define SW128(b) ((b) ^ ((((uint32_t)(b)) >> 3) & 0x70))

// ---------------------------------------------------------------------------
// Prep kernels
// ---------------------------------------------------------------------------
__global__ void cvt_tf32_kernel(const float* __restrict__ in, uint32_t* __restrict__ outp, int n4)
{
    int i = blockIdx.x * blockDim.x + threadIdx.x;
    if (i < n4) {
        float4 v = ((const float4*)in)[i];
        uint4 u;
        u.x = f2tf(v.x); u.y = f2tf(v.y); u.z = f2tf(v.z); u.w = f2tf(v.w);
        ((uint4*)outp)[i] = u;
    }
}

// in [R][C] fp32 -> out [C][R] tf32 bits
__global__ void transpose_cvt_kernel(const float* __restrict__ in, uint32_t* __restrict__ outp,
                                     int R, int C)
{
    __shared__ uint32_t t[32][33];
    const int bx = blockIdx.x * 32;
    const int by = blockIdx.y * 32;
    #pragma unroll
    for (int j = 0; j < 4; j++)
        t[threadIdx.y + j * 8][threadIdx.x] =
            f2tf(in[(size_t)(by + threadIdx.y + j * 8) * C + bx + threadIdx.x]);
    __syncthreads();
    #pragma unroll
    for (int j = 0; j < 4; j++)
        outp[(size_t)(bx + threadIdx.y + j * 8) * R + by + threadIdx.x] =
            t[threadIdx.x][threadIdx.y + j * 8];
}

// ---------------------------------------------------------------------------
// RoPE v2: fused rope + tf32 convert (validated round 7).
// ---------------------------------------------------------------------------
__global__ void __launch_bounds__(256) rope_cvt_kernel(
    const float* __restrict__ qkv,
    uint32_t* __restrict__ q32, uint32_t* __restrict__ k32, uint32_t* __restrict__ v32)
{
    __shared__ float cs[64], sn[64];
    const int bs = blockIdx.x;
    const int t  = threadIdx.x;
    const int s  = bs & (SS - 1);

    if (t < 64) {
        const float inv_freq = exp2f(-(float)t * 0.311430758895690262f);
        sincosf((float)s * inv_freq, &sn[t], &cs[t]);
    }
    __syncthreads();

    const float* row = qkv + (size_t)bs * QKVW;
    const float scale = 0.088388347648318447f;  // 1/sqrt(128)

    for (int p = t; p < (HH + KVH) * 64; p += 256) {
        const int head = p >> 6;
        const int d    = p & 63;
        const float* base = row + (head < HH ? head * DD : HH * DD + (head - HH) * DD);
        const float x0 = base[d];
        const float x1 = base[d + 64];
        const float r0 = x0 * cs[d] - x1 * sn[d];
        const float r1 = x1 * cs[d] + x0 * sn[d];
        if (head < HH) {
            uint32_t* dst = q32 + (size_t)bs * (HH * DD) + head * DD;
            dst[d]      = f2tf(r0 * scale);
            dst[d + 64] = f2tf(r1 * scale);
        } else {
            uint32_t* dst = k32 + (size_t)bs * (KVH * DD) + (head - HH) * DD;
            dst[d]      = f2tf(r0);
            dst[d + 64] = f2tf(r1);
        }
    }
    for (int i = t; i < KVH * DD; i += 256)
        v32[(size_t)bs * (KVH * DD) + i] = f2tf(row[(HH + KVH) * DD + i]);
}

// ---------------------------------------------------------------------------
// TF32 mma.sync GEMM v5 (validated round 8 — unchanged).
// ---------------------------------------------------------------------------
#define AST_BYTES 32768u
#define BST_BYTES 16384u
#define STG_BYTES 49152u
#define NSTAGE    3
#define GEMM_SMEM (NSTAGE * STG_BYTES)

__global__ void __launch_bounds__(256) gemm_tf32_v5(
    const uint32_t* __restrict__ A, const uint32_t* __restrict__ Bt,
    float* __restrict__ C, int M, int N, int K)
{
    extern __shared__ uint32_t smu[];
    uint32_t smem_base;
    asm("{ .reg .u64 t; cvta.to.shared.u64 t, %1; cvt.u32.u64 %0, t; }"
        : "=r"(smem_base) : "l"(smu));

    const int tid    = threadIdx.x;
    const int warp   = tid >> 5;
    const int lane   = tid & 31;
    const int g      = lane >> 2;
    const int l4     = lane & 3;
    const int r      = lane & 7;
    const int q      = lane >> 3;
    const int warp_m = warp >> 1;
    const int warp_n = warp & 1;
    const int bm     = blockIdx.y * 256;
    const int bn     = blockIdx.x * 128;

    const uint32_t xr = (uint32_t)r << 4;

    uint32_t relA[4], relB[4];
    #pragma unroll
    for (int mt = 0; mt < 4; mt++)
        relA[mt] = (uint32_t)(warp_m * 64 + mt * 16 + r + (q & 1) * 8) * 128;
    #pragma unroll
    for (int p = 0; p < 4; p++)
        relB[p] = (uint32_t)(warp_n * 64 + p * 16 + r + (q >> 1) * 8) * 128;
    const uint32_t colA = (uint32_t)(q >> 1) * 16;
    const uint32_t colB = (uint32_t)(q & 1) * 16;

    const int ntiles = K / 32;

    auto issue_stage = [&](int s) {
        const uint32_t stgA = smem_base + (uint32_t)(s % NSTAGE) * STG_BYTES;
        const uint32_t stgB = stgA + AST_BYTES;
        const int k0 = s * 32;
        #pragma unroll
        for (int i = 0; i < 8; i++) {
            const int idx = tid + i * 256;
            const int row = idx >> 3;
            const int ch  = idx & 7;
            const uint32_t byte = (uint32_t)row * 128 + (uint32_t)ch * 16;
            cp_async_16(stgA + SW128(byte), &A[(size_t)(bm + row) * K + k0 + ch * 4]);
        }
        #pragma unroll
        for (int i = 0; i < 4; i++) {
            const int idx = tid + i * 256;
            const int row = idx >> 3;
            const int ch  = idx & 7;
            const uint32_t byte = (uint32_t)row * 128 + (uint32_t)ch * 16;
            cp_async_16(stgB + SW128(byte), &Bt[(size_t)(bn + row) * K + k0 + ch * 4]);
        }
        CP_COMMIT();
    };

    float acc[4][8][4];
    #pragma unroll
    for (int mt = 0; mt < 4; mt++)
        #pragma unroll
        for (int nt = 0; nt < 8; nt++)
            #pragma unroll
            for (int i = 0; i < 4; i++) acc[mt][nt][i] = 0.f;

    issue_stage(0);
    issue_stage(1);

    for (int it = 0; it < ntiles; it++) {
        if (it + 1 < ntiles) CP_WAIT(1); else CP_WAIT(0);
        __syncthreads();
        if (it + 2 < ntiles) issue_stage(it + 2);

        const uint32_t stgA = smem_base + (uint32_t)(it % NSTAGE) * STG_BYTES;
        const uint32_t stgB = stgA + AST_BYTES;

        #pragma unroll
        for (int kk = 0; kk < 4; kk++) {
            const uint32_t offA = ((uint32_t)kk * 32 + colA) ^ xr;
            const uint32_t offB = ((uint32_t)kk * 32 + colB) ^ xr;
            uint32_t af[4][4], bf[8][2];
            #pragma unroll
            for (int mt = 0; mt < 4; mt++)
                ldsm4(af[mt], stgA + relA[mt] + offA);
            #pragma unroll
            for (int p = 0; p < 4; p++) {
                uint32_t bq[4];
                ldsm4(bq, stgB + relB[p] + offB);
                bf[2 * p][0]     = bq[0];
                bf[2 * p][1]     = bq[1];
                bf[2 * p + 1][0] = bq[2];
                bf[2 * p + 1][1] = bq[3];
            }
            #pragma unroll
            for (int mt = 0; mt < 4; mt++)
                #pragma unroll
                for (int nt = 0; nt < 8; nt++)
                    mma_tf32(acc[mt][nt], af[mt], bf[nt]);
        }
    }

    #pragma unroll
    for (int mt = 0; mt < 4; mt++) {
        const int row0 = bm + warp_m * 64 + mt * 16 + g;
        #pragma unroll
        for (int nt = 0; nt < 8; nt++) {
            const int col = bn + warp_n * 64 + nt * 8 + 2 * l4;
            *(float2*)&C[(size_t)row0 * N + col] =
                make_float2(acc[mt][nt][0], acc[mt][nt][1]);
            *(float2*)&C[(size_t)(row0 + 8) * N + col] =
                make_float2(acc[mt][nt][2], acc[mt][nt][3]);
        }
    }
}

// ---------------------------------------------------------------------------
// Flash attention v3: 4-warp CTAs (BQ=64), 32-key double-buffered KV tiles,
// 66KB smem -> 2 CTAs/SM so softmax/barrier bubbles of one CTA overlap the
// other CTA's tensor work.
// ---------------------------------------------------------------------------
#define BQA 64
#define KTA 32
#define MASKVAL -3.0e38f
#define AK_BYTES 16384u    // 32 keys x 128B (SW128, 4 stacked d-blocks)
#define AV_BYTES 17408u    // 32 keys x 136 words
#define ATT_SMEM (2 * AK_BYTES + 2 * AV_BYTES)   // 67584

__global__ void __launch_bounds__(128, 2) attn_tc_v3(
    const uint32_t* __restrict__ q32, const uint32_t* __restrict__ k32,
    const uint32_t* __restrict__ v32, uint32_t* __restrict__ out)
{
    extern __shared__ uint32_t smem[];
    uint32_t smb;
    asm("{ .reg .u64 t; cvta.to.shared.u64 t, %1; cvt.u32.u64 %0, t; }"
        : "=r"(smb) : "l"(smem));

    const int tid  = threadIdx.x;
    const int warp = tid >> 5;        // 0..3
    const int lane = tid & 31;
    const int g    = lane >> 2;
    const int l4   = lane & 3;
    const int r    = lane & 7;
    const int qq   = lane >> 3;
    const int b    = blockIdx.z;
    const int h    = blockIdx.y;
    const int q0   = blockIdx.x * BQA;
    const int gkv  = h >> 2;

    const uint32_t kbuf[2] = { 0u, AK_BYTES };
    const uint32_t vbuf[2] = { 2 * AK_BYTES, 2 * AK_BYTES + AV_BYTES };

    // ---- Q staging (64 rows x 128 cols, stride 132, before KV pipeline) ----
    uint32_t* Qs = smem;
    for (int idx = tid; idx < 64 * 32; idx += 128) {
        const int rr = idx >> 5, c4 = (idx & 31) << 2;
        *(uint4*)&Qs[rr * 132 + c4] =
            *(const uint4*)&q32[(size_t)(b * SS + q0 + rr) * (HH * DD) + h * DD + c4];
    }
    __syncthreads();
    uint32_t qf[16][4];
    {
        const int lr = warp * 16;
        #pragma unroll
        for (int k = 0; k < 16; k++) {
            qf[k][0] = Qs[(lr + g)     * 132 + k * 8 + l4];
            qf[k][1] = Qs[(lr + g + 8) * 132 + k * 8 + l4];
            qf[k][2] = Qs[(lr + g)     * 132 + k * 8 + l4 + 4];
            qf[k][3] = Qs[(lr + g + 8) * 132 + k * 8 + l4 + 4];
        }
    }
    __syncthreads();

    const int js    = max(0, q0 - WINW);
    const int ntile = (q0 + BQA - js) >> 5;   // tiles of 32 keys

    // K fragment addressing (B-operand pattern validated in gemm v3/v5)
    const uint32_t xr = (uint32_t)r << 4;
    uint32_t relK[2];
    #pragma unroll
    for (int p = 0; p < 2; p++)
        relK[p] = (uint32_t)(p * 16 + r + (qq >> 1) * 8) * 128;
    const uint32_t colK = (uint32_t)(qq & 1) * 16;

    auto issue_tile = [&](int t) {
        const int kt0 = js + t * KTA;
        const uint32_t kb = smb + kbuf[t & 1];
        const uint32_t vb = smb + vbuf[t & 1];
        #pragma unroll
        for (int i = 0; i < 8; i++) {
            const int idx = tid + i * 128;
            const int key = idx >> 5, c = idx & 31;
            const uint32_t byte = (uint32_t)((c >> 3) * 32 + key) * 128 + (uint32_t)(c & 7) * 16;
            cp_async_16(kb + SW128(byte),
                &k32[((size_t)(b * SS + kt0 + key) * KVH + gkv) * DD + c * 4]);
        }
        #pragma unroll
        for (int i = 0; i < 8; i++) {
            const int idx = tid + i * 128;
            const int key = idx >> 5, c = idx & 31;
            cp_async_16(vb + (uint32_t)(key * 136 + c * 4) * 4,
                &v32[((size_t)(b * SS + kt0 + key) * KVH + gkv) * DD + c * 4]);
        }
        CP_COMMIT();
    };

    float o[16][4];
    #pragma unroll
    for (int dt = 0; dt < 16; dt++)
        #pragma unroll
        for (int i = 0; i < 4; i++) o[dt][i] = 0.f;
    float m_a = -1e30f, m_b = -1e30f, l_a = 0.f, l_b = 0.f;

    const int i_lo = q0 + warp * 16;
    const int i_a  = i_lo + g;
    const int i_b  = i_a + 8;

    issue_tile(0);

    for (int t = 0; t < ntile; t++) {
        CP_WAIT(0);
        __syncthreads();
        if (t + 1 < ntile) issue_tile(t + 1);

        const int kt0 = js + t * KTA;
        const uint32_t kb = smb + kbuf[t & 1];
        const uint32_t* Vs = smem + (vbuf[t & 1] >> 2);

        // ---- S = Q K^T ----
        float s[4][4];
        #pragma unroll
        for (int nt = 0; nt < 4; nt++)
            #pragma unroll
            for (int i = 0; i < 4; i++) s[nt][i] = 0.f;

        #pragma unroll
        for (int kk = 0; kk < 16; kk++) {
            const uint32_t rowb = kb + (uint32_t)(kk >> 2) * (32 * 128);
            const uint32_t offK = ((uint32_t)(kk & 3) * 32 + colK) ^ xr;
            uint32_t bf[4][2];
            #pragma unroll
            for (int p = 0; p < 2; p++) {
                uint32_t bq[4];
                ldsm4(bq, rowb + relK[p] + offK);
                bf[2*p][0] = bq[0]; bf[2*p][1] = bq[1];
                bf[2*p+1][0] = bq[2]; bf[2*p+1][1] = bq[3];
            }
            #pragma unroll
            for (int nt = 0; nt < 4; nt++)
                mma_tf32(s[nt], qf[kk], bf[nt]);
        }

        // ---- mask ----
        #pragma unroll
        for (int nt = 0; nt < 4; nt++) {
            const int j0 = kt0 + nt * 8;
            const bool allvalid = (j0 + 7 <= i_lo) && (i_lo + 15 - j0 < WINW);
            if (!allvalid) {
                const int ja = j0 + 2 * l4, jb = ja + 1;
                if (!(ja <= i_a && i_a - ja < WINW)) s[nt][0] = MASKVAL;
                if (!(jb <= i_a && i_a - jb < WINW)) s[nt][1] = MASKVAL;
                if (!(ja <= i_b && i_b - ja < WINW)) s[nt][2] = MASKVAL;
                if (!(jb <= i_b && i_b - jb < WINW)) s[nt][3] = MASKVAL;
            }
        }

        // ---- online softmax ----
        float ta = MASKVAL, tb = MASKVAL;
        #pragma unroll
        for (int nt = 0; nt < 4; nt++) {
            ta = fmaxf(ta, fmaxf(s[nt][0], s[nt][1]));
            tb = fmaxf(tb, fmaxf(s[nt][2], s[nt][3]));
        }
        ta = fmaxf(ta, __shfl_xor_sync(0xffffffffu, ta, 1));
        ta = fmaxf(ta, __shfl_xor_sync(0xffffffffu, ta, 2));
        tb = fmaxf(tb, __shfl_xor_sync(0xffffffffu, tb, 1));
        tb = fmaxf(tb, __shfl_xor_sync(0xffffffffu, tb, 2));

        const float mna = fmaxf(m_a, ta);
        const float mnb = fmaxf(m_b, tb);
        const float alpha_a = __expf(m_a - mna);
        const float alpha_b = __expf(m_b - mnb);
        m_a = mna; m_b = mnb;

        float ra = 0.f, rb = 0.f;
        #pragma unroll
        for (int nt = 0; nt < 4; nt++) {
            s[nt][0] = __expf(s[nt][0] - m_a);
            s[nt][1] = __expf(s[nt][1] - m_a);
            s[nt][2] = __expf(s[nt][2] - m_b);
            s[nt][3] = __expf(s[nt][3] - m_b);
            ra += s[nt][0] + s[nt][1];
            rb += s[nt][2] + s[nt][3];
        }
        ra += __shfl_xor_sync(0xffffffffu, ra, 1);
        ra += __shfl_xor_sync(0xffffffffu, ra, 2);
        rb += __shfl_xor_sync(0xffffffffu, rb, 1);
        rb += __shfl_xor_sync(0xffffffffu, rb, 2);
        l_a = l_a * alpha_a + ra;
        l_b = l_b * alpha_b + rb;

        #pragma unroll
        for (int dt = 0; dt < 16; dt++) {
            o[dt][0] *= alpha_a; o[dt][1] *= alpha_a;
            o[dt][2] *= alpha_b; o[dt][3] *= alpha_b;
        }

        // ---- O += P V ----
        const int src0 = (lane & ~3) | (l4 >> 1);
        const int src1 = src0 + 2;
        const bool odd = (l4 & 1);
        #pragma unroll
        for (int nt = 0; nt < 4; nt++) {
            float u0 = __shfl_sync(0xffffffffu, s[nt][0], src0);
            float u1 = __shfl_sync(0xffffffffu, s[nt][1], src0);
            float w0 = __shfl_sync(0xffffffffu, s[nt][0], src1);
            float w1 = __shfl_sync(0xffffffffu, s[nt][1], src1);
            float x0 = __shfl_sync(0xffffffffu, s[nt][2], src0);
            float x1 = __shfl_sync(0xffffffffu, s[nt][3], src0);
            float y0 = __shfl_sync(0xffffffffu, s[nt][2], src1);
            float y1 = __shfl_sync(0xffffffffu, s[nt][3], src1);
            uint32_t ap[4];
            ap[0] = f2tf(odd ? u1 : u0);
            ap[1] = f2tf(odd ? x1 : x0);
            ap[2] = f2tf(odd ? w1 : w0);
            ap[3] = f2tf(odd ? y1 : y0);
            #pragma unroll
            for (int dt = 0; dt < 16; dt++) {
                uint32_t bfr[2];
                bfr[0] = Vs[(nt * 8 + l4)     * 136 + dt * 8 + g];
                bfr[1] = Vs[(nt * 8 + l4 + 4) * 136 + dt * 8 + g];
                mma_tf32(o[dt], ap, bfr);
            }
        }
    }

    const float inv_a = 1.0f / l_a;
    const float inv_b = 1.0f / l_b;
    #pragma unroll
    for (int dt = 0; dt < 16; dt++) {
        const int col = h * DD + dt * 8 + 2 * l4;
        *(uint2*)&out[(size_t)(b * SS + i_a) * (HH * DD) + col] =
            make_uint2(f2tf(o[dt][0] * inv_a), f2tf(o[dt][1] * inv_a));
        *(uint2*)&out[(size_t)(b * SS + i_b) * (HH * DD) + col] =
            make_uint2(f2tf(o[dt][2] * inv_b), f2tf(o[dt][3] * inv_b));
    }
}

// ---------------------------------------------------------------------------
extern "C" void kernel_launch(void* const* d_in, const int* in_sizes, int n_in,
                              void* d_out, int out_size)
{
    const float* x     = (const float*)d_in[0];
    const float* w_qkv = (const float*)d_in[1];
    const float* w_o   = (const float*)d_in[2];
    float* out = (float*)d_out;

    float*    qkv_ptr  = nullptr;
    uint32_t* attn_ptr = nullptr;
    uint32_t* x32_ptr  = nullptr;
    uint32_t* wqkvT    = nullptr;
    uint32_t* woT      = nullptr;
    uint32_t* q32_ptr  = nullptr;
    uint32_t* k32_ptr  = nullptr;
    uint32_t* v32_ptr  = nullptr;
    cudaGetSymbolAddress((void**)&qkv_ptr,  g_qkv);
    cudaGetSymbolAddress((void**)&attn_ptr, g_attn);
    cudaGetSymbolAddress((void**)&x32_ptr,  g_x32);
    cudaGetSymbolAddress((void**)&wqkvT,    g_wqkvT);
    cudaGetSymbolAddress((void**)&woT,      g_woT);
    cudaGetSymbolAddress((void**)&q32_ptr,  g_q32);
    cudaGetSymbolAddress((void**)&k32_ptr,  g_k32);
    cudaGetSymbolAddress((void**)&v32_ptr,  g_v32);

    cudaFuncSetAttribute(gemm_tf32_v5,
                         cudaFuncAttributeMaxDynamicSharedMemorySize, GEMM_SMEM);
    cudaFuncSetAttribute(attn_tc_v3,
                         cudaFuncAttributeMaxDynamicSharedMemorySize, ATT_SMEM);

    // 0) prep: x -> tf32; weights -> transposed tf32 [N][K]
    {
        int n4 = (NROWS * EE) / 4;
        cvt_tf32_kernel<<<(n4 + 255) / 256, 256>>>(x, x32_ptr, n4);
        dim3 blk(32, 8);
        transpose_cvt_kernel<<<dim3(QKVW / 32, EE / 32), blk>>>(w_qkv, wqkvT, EE, QKVW);
        transpose_cvt_kernel<<<dim3(EE / 32, EE / 32), blk>>>(w_o, woT, EE, EE);
    }
    // 1) QKV projection
    {
        dim3 grid(QKVW / 128, NROWS / 256);
        gemm_tf32_v5<<<grid, 256, GEMM_SMEM>>>(x32_ptr, wqkvT, qkv_ptr, NROWS, QKVW, EE);
    }
    // 2) RoPE + tf32 split buffers
    {
        rope_cvt_kernel<<<NROWS, 256>>>(qkv_ptr, q32_ptr, k32_ptr, v32_ptr);
    }
    // 3) Flash attention v3 (2 CTAs/SM)
    {
        dim3 grid(SS / BQA, HH, BB);
        attn_tc_v3<<<grid, 128, ATT_SMEM>>>(q32_ptr, k32_ptr, v32_ptr, attn_ptr);
    }
    // 4) Output projection
    {
        dim3 grid(EE / 128, NROWS / 256);
        gemm_tf32_v5<<<grid, 256, GEMM_SMEM>>>(attn_ptr, woT, out, NROWS, EE, EE);
    }
}

// round 10
// speedup vs baseline: 7.9316x; 1.7932x over previous
#include <cuda_runtime.h>
#include <cuda_fp16.h>
#include <math.h>
#include <stdint.h>

// Problem constants
#define BB   2
#define SS   2048
#define EE   2048
#define HH   16
#define KVH  4
#define DD   128
#define WINW 512
#define QKVW ((HH + 2*KVH) * DD)   // 3072
#define NROWS (BB * SS)            // 4096

// Scratch (static device globals)
__device__ float  g_qkv[(size_t)NROWS * QKVW];          // fp32 qkv (pre-RoPE)
__device__ __half g_attn_h[(size_t)NROWS * HH * DD];    // attn out (half)
__device__ __half g_xh[(size_t)NROWS * EE];             // x (half) [M][K]
__device__ __half g_wqkvT_h[(size_t)QKVW * EE];         // w_qkv^T (half) [N][K]
__device__ __half g_woT_h[(size_t)EE * EE];             // w_o^T (half) [N][K]
__device__ __half g_q16[(size_t)NROWS * HH * DD];       // roped+scaled Q half
__device__ __half g_k16[(size_t)NROWS * KVH * DD];      // roped K half
__device__ __half g_vT[(size_t)BB * KVH * DD * SS];     // V half, [b][kv][d][s]

__device__ __forceinline__ uint32_t pack2h(float a, float b) {
    __half2 h = __floats2half2_rn(a, b);
    return *(uint32_t*)&h;
}

__device__ __forceinline__ void mma_f16(float* c, const uint32_t* a, const uint32_t* b) {
    asm volatile(
        "mma.sync.aligned.m16n8k16.row.col.f32.f16.f16.f32 "
        "{%0,%1,%2,%3}, {%4,%5,%6,%7}, {%8,%9}, {%0,%1,%2,%3};\n"
        : "+f"(c[0]), "+f"(c[1]), "+f"(c[2]), "+f"(c[3])
        : "r"(a[0]), "r"(a[1]), "r"(a[2]), "r"(a[3]), "r"(b[0]), "r"(b[1]));
}

__device__ __forceinline__ void ldsm4(uint32_t* d, uint32_t a) {
    asm volatile("ldmatrix.sync.aligned.m8n8.x4.shared.b16 {%0,%1,%2,%3}, [%4];"
        : "=r"(d[0]), "=r"(d[1]), "=r"(d[2]), "=r"(d[3]) : "r"(a));
}

__device__ __forceinline__ void cp_async_16(uint32_t smem_addr, const void* gptr) {
    asm volatile("cp.async.cg.shared.global [%0], [%1], 16;" :: "r"(smem_addr), "l"(gptr));
}

#define CP_COMMIT()  asm volatile("cp.async.commit_group;" ::: "memory")
#define CP_WAIT(n)   asm volatile("cp.async.wait_group %0;" :: "n"(n) : "memory")

#define SW128(b) ((b) ^ ((((uint32_t)(b)) >> 3) & 0x70))

// ---------------------------------------------------------------------------
// Prep: fp32 -> half
// ---------------------------------------------------------------------------
__global__ void cvt_half_kernel(const float* __restrict__ in, __half* __restrict__ outp, int n4)
{
    int i = blockIdx.x * blockDim.x + threadIdx.x;
    if (i < n4) {
        float4 v = ((const float4*)in)[i];
        uint2 u;
        u.x = pack2h(v.x, v.y);
        u.y = pack2h(v.z, v.w);
        ((uint2*)outp)[i] = u;
    }
}

// in [R][C] fp32 -> out [C][R] half
__global__ void transpose_cvt_h_kernel(const float* __restrict__ in, __half* __restrict__ outp,
                                       int R, int C)
{
    __shared__ __half t[32][34];
    const int bx = blockIdx.x * 32;
    const int by = blockIdx.y * 32;
    #pragma unroll
    for (int j = 0; j < 4; j++)
        t[threadIdx.y + j * 8][threadIdx.x] =
            __float2half_rn(in[(size_t)(by + threadIdx.y + j * 8) * C + bx + threadIdx.x]);
    __syncthreads();
    #pragma unroll
    for (int j = 0; j < 4; j++)
        outp[(size_t)(bx + threadIdx.y + j * 8) * R + by + threadIdx.x] =
            t[threadIdx.x][threadIdx.y + j * 8];
}

// V transpose: g_qkv V slice [s][c=kv*128+d] (per batch) -> vT[(b*512+c)][s] half
__global__ void vtrans_kernel(const float* __restrict__ qkv, __half* __restrict__ vT)
{
    __shared__ __half t[32][34];
    const int b  = blockIdx.z;
    const int bx = blockIdx.x * 32;   // c base
    const int by = blockIdx.y * 32;   // s base
    #pragma unroll
    for (int j = 0; j < 4; j++)
        t[threadIdx.y + j * 8][threadIdx.x] =
            __float2half_rn(qkv[(size_t)(b * SS + by + threadIdx.y + j * 8) * QKVW
                                + (HH + KVH) * DD + bx + threadIdx.x]);
    __syncthreads();
    #pragma unroll
    for (int j = 0; j < 4; j++)
        vT[(size_t)(b * (KVH * DD) + bx + threadIdx.y + j * 8) * SS + by + threadIdx.x] =
            t[threadIdx.x][threadIdx.y + j * 8];
}

// ---------------------------------------------------------------------------
// RoPE v3: fused rope + half convert. q -> g_q16 (scale folded), k -> g_k16.
// ---------------------------------------------------------------------------
__global__ void __launch_bounds__(256) rope_cvt_kernel(
    const float* __restrict__ qkv,
    __half* __restrict__ q16, __half* __restrict__ k16)
{
    __shared__ float cs[64], sn[64];
    const int bs = blockIdx.x;
    const int t  = threadIdx.x;
    const int s  = bs & (SS - 1);

    if (t < 64) {
        const float inv_freq = exp2f(-(float)t * 0.311430758895690262f);
        sincosf((float)s * inv_freq, &sn[t], &cs[t]);
    }
    __syncthreads();

    const float* row = qkv + (size_t)bs * QKVW;
    const float scale = 0.088388347648318447f;  // 1/sqrt(128)

    for (int p = t; p < (HH + KVH) * 64; p += 256) {
        const int head = p >> 6;
        const int d    = p & 63;
        const float* base = row + (head < HH ? head * DD : HH * DD + (head - HH) * DD);
        const float x0 = base[d];
        const float x1 = base[d + 64];
        const float r0 = x0 * cs[d] - x1 * sn[d];
        const float r1 = x1 * cs[d] + x0 * sn[d];
        if (head < HH) {
            __half* dst = q16 + (size_t)bs * (HH * DD) + head * DD;
            dst[d]      = __float2half_rn(r0 * scale);
            dst[d + 64] = __float2half_rn(r1 * scale);
        } else {
            __half* dst = k16 + (size_t)bs * (KVH * DD) + (head - HH) * DD;
            dst[d]      = __float2half_rn(r0);
            dst[d + 64] = __float2half_rn(r1);
        }
    }
}

// ---------------------------------------------------------------------------
// FP16 mma.sync GEMM v6: C[M,N] = A[M,K] * Bt[N,K]^T   (K in halves)
// Identical byte layout to validated v5 (SW128 128-byte rows), but each row
// now holds K=64 halves -> BK=64, mma m16n8k16, half the k-tiles.
// CTA 256x128, 8 warps (4m x 2n), warp tile 64x64, 3-stage cp.async.
// ---------------------------------------------------------------------------
#define AST_BYTES 32768u
#define STG_BYTES 49152u
#define NSTAGE    3
#define GEMM_SMEM (NSTAGE * STG_BYTES)

__global__ void __launch_bounds__(256) gemm_f16_v6(
    const __half* __restrict__ A, const __half* __restrict__ Bt,
    float* __restrict__ C, int M, int N, int K)
{
    extern __shared__ uint32_t smu[];
    uint32_t smem_base;
    asm("{ .reg .u64 t; cvta.to.shared.u64 t, %1; cvt.u32.u64 %0, t; }"
        : "=r"(smem_base) : "l"(smu));

    const int tid    = threadIdx.x;
    const int warp   = tid >> 5;
    const int lane   = tid & 31;
    const int g      = lane >> 2;
    const int l4     = lane & 3;
    const int r      = lane & 7;
    const int q      = lane >> 3;
    const int warp_m = warp >> 1;
    const int warp_n = warp & 1;
    const int bm     = blockIdx.y * 256;
    const int bn     = blockIdx.x * 128;

    const uint32_t xr = (uint32_t)r << 4;

    uint32_t relA[4], relB[4];
    #pragma unroll
    for (int mt = 0; mt < 4; mt++)
        relA[mt] = (uint32_t)(warp_m * 64 + mt * 16 + r + (q & 1) * 8) * 128;
    #pragma unroll
    for (int p = 0; p < 4; p++)
        relB[p] = (uint32_t)(warp_n * 64 + p * 16 + r + (q >> 1) * 8) * 128;
    const uint32_t colA = (uint32_t)(q >> 1) * 16;
    const uint32_t colB = (uint32_t)(q & 1) * 16;

    const int ntiles = K / 64;   // 32

    auto issue_stage = [&](int s) {
        const uint32_t stgA = smem_base + (uint32_t)(s % NSTAGE) * STG_BYTES;
        const uint32_t stgB = stgA + AST_BYTES;
        const int k0 = s * 64;
        #pragma unroll
        for (int i = 0; i < 8; i++) {
            const int idx = tid + i * 256;
            const int row = idx >> 3;
            const int ch  = idx & 7;
            const uint32_t byte = (uint32_t)row * 128 + (uint32_t)ch * 16;
            cp_async_16(stgA + SW128(byte), &A[(size_t)(bm + row) * K + k0 + ch * 8]);
        }
        #pragma unroll
        for (int i = 0; i < 4; i++) {
            const int idx = tid + i * 256;
            const int row = idx >> 3;
            const int ch  = idx & 7;
            const uint32_t byte = (uint32_t)row * 128 + (uint32_t)ch * 16;
            cp_async_16(stgB + SW128(byte), &Bt[(size_t)(bn + row) * K + k0 + ch * 8]);
        }
        CP_COMMIT();
    };

    float acc[4][8][4];
    #pragma unroll
    for (int mt = 0; mt < 4; mt++)
        #pragma unroll
        for (int nt = 0; nt < 8; nt++)
            #pragma unroll
            for (int i = 0; i < 4; i++) acc[mt][nt][i] = 0.f;

    issue_stage(0);
    issue_stage(1);

    for (int it = 0; it < ntiles; it++) {
        if (it + 1 < ntiles) CP_WAIT(1); else CP_WAIT(0);
        __syncthreads();
        if (it + 2 < ntiles) issue_stage(it + 2);

        const uint32_t stgA = smem_base + (uint32_t)(it % NSTAGE) * STG_BYTES;
        const uint32_t stgB = stgA + AST_BYTES;

        #pragma unroll
        for (int kk = 0; kk < 4; kk++) {      // 4 x k16 = K64
            const uint32_t offA = ((uint32_t)kk * 32 + colA) ^ xr;
            const uint32_t offB = ((uint32_t)kk * 32 + colB) ^ xr;
            uint32_t af[4][4], bf[8][2];
            #pragma unroll
            for (int mt = 0; mt < 4; mt++)
                ldsm4(af[mt], stgA + relA[mt] + offA);
            #pragma unroll
            for (int p = 0; p < 4; p++) {
                uint32_t bq[4];
                ldsm4(bq, stgB + relB[p] + offB);
                bf[2 * p][0]     = bq[0];
                bf[2 * p][1]     = bq[1];
                bf[2 * p + 1][0] = bq[2];
                bf[2 * p + 1][1] = bq[3];
            }
            #pragma unroll
            for (int mt = 0; mt < 4; mt++)
                #pragma unroll
                for (int nt = 0; nt < 8; nt++)
                    mma_f16(acc[mt][nt], af[mt], bf[nt]);
        }
    }

    #pragma unroll
    for (int mt = 0; mt < 4; mt++) {
        const int row0 = bm + warp_m * 64 + mt * 16 + g;
        #pragma unroll
        for (int nt = 0; nt < 8; nt++) {
            const int col = bn + warp_n * 64 + nt * 8 + 2 * l4;
            *(float2*)&C[(size_t)row0 * N + col] =
                make_float2(acc[mt][nt][0], acc[mt][nt][1]);
            *(float2*)&C[(size_t)(row0 + 8) * N + col] =
                make_float2(acc[mt][nt][2], acc[mt][nt][3]);
        }
    }
}

// ---------------------------------------------------------------------------
// FP16 flash attention v4: 4-warp CTAs (BQ=64), 32-key double-buffered tiles,
// 2 CTAs/SM. No P shuffles (fp16 A-frag == softmax C-frag rows), V via
// ldmatrix from pre-transposed vT.
// ---------------------------------------------------------------------------
#define BQA 64
#define KTA 32
#define MASKVAL -3.0e38f
#define QSTRH  152                 // Q smem row stride in halves (304B, 16B mult)
#define Q_BYTES  (64 * QSTRH * 2)  // 19456
#define K_BYTES  8192u             // 2 d-blocks x 32 keys x 128B
#define V_BYTES  10240u            // 128 d rows x 80B
#define OFF_K0   ((uint32_t)Q_BYTES)
#define OFF_K1   (OFF_K0 + K_BYTES)
#define OFF_V0   (OFF_K1 + K_BYTES)
#define OFF_V1   (OFF_V0 + V_BYTES)
#define ATT_SMEM (OFF_V1 + V_BYTES)   // 56320

__global__ void __launch_bounds__(128, 2) attn_f16_v4(
    const __half* __restrict__ q16, const __half* __restrict__ k16,
    const __half* __restrict__ vT, __half* __restrict__ out)
{
    extern __shared__ uint32_t smem[];
    uint32_t smb;
    asm("{ .reg .u64 t; cvta.to.shared.u64 t, %1; cvt.u32.u64 %0, t; }"
        : "=r"(smb) : "l"(smem));
    __half* Qsh = (__half*)smem;

    const int tid  = threadIdx.x;
    const int warp = tid >> 5;
    const int lane = tid & 31;
    const int g    = lane >> 2;
    const int l4   = lane & 3;
    const int r    = lane & 7;
    const int qq   = lane >> 3;
    const int b    = blockIdx.z;
    const int h    = blockIdx.y;
    const int q0   = blockIdx.x * BQA;
    const int gkv  = h >> 2;

    // ---- Q staging (64 rows x 128 halves, stride QSTRH) ----
    for (int idx = tid; idx < 64 * 16; idx += 128) {
        const int rr = idx >> 4, c8 = idx & 15;
        *(uint4*)&Qsh[rr * QSTRH + c8 * 8] =
            *(const uint4*)&q16[(size_t)(b * SS + q0 + rr) * (HH * DD) + h * DD + c8 * 8];
    }
    __syncthreads();
    uint32_t qf[8][4];
    {
        const int lr = warp * 16;
        #pragma unroll
        for (int kk = 0; kk < 8; kk++) {
            qf[kk][0] = *(const uint32_t*)&Qsh[(lr + g)     * QSTRH + kk * 16 + 2 * l4];
            qf[kk][1] = *(const uint32_t*)&Qsh[(lr + g + 8) * QSTRH + kk * 16 + 2 * l4];
            qf[kk][2] = *(const uint32_t*)&Qsh[(lr + g)     * QSTRH + kk * 16 + 8 + 2 * l4];
            qf[kk][3] = *(const uint32_t*)&Qsh[(lr + g + 8) * QSTRH + kk * 16 + 8 + 2 * l4];
        }
    }
    __syncthreads();

    const int js    = max(0, q0 - WINW);
    const int ntile = (q0 + BQA - js) >> 5;

    const uint32_t xr = (uint32_t)r << 4;
    uint32_t relK[2];
    #pragma unroll
    for (int p = 0; p < 2; p++)
        relK[p] = (uint32_t)(p * 16 + r + (qq >> 1) * 8) * 128;
    const uint32_t colK = (uint32_t)(qq & 1) * 16;

    auto issue_tile = [&](int t) {
        const int kt0 = js + t * KTA;
        const uint32_t kb = smb + (t & 1 ? OFF_K1 : OFF_K0);
        const uint32_t vb = smb + (t & 1 ? OFF_V1 : OFF_V0);
        // K: 32 keys x 128 halves; 16B chunk c (0..15), d-block = c>>3
        #pragma unroll
        for (int i = 0; i < 4; i++) {
            const int idx = tid + i * 128;
            const int key = idx >> 4, c = idx & 15;
            const uint32_t byte = (uint32_t)((c >> 3) * 32 + key) * 128 + (uint32_t)(c & 7) * 16;
            cp_async_16(kb + SW128(byte),
                &k16[((size_t)(b * SS + kt0 + key) * KVH + gkv) * DD + c * 8]);
        }
        // V: 128 d rows x 32 keys (64B), row stride 80B
        #pragma unroll
        for (int i = 0; i < 4; i++) {
            const int idx = tid + i * 128;
            const int d = idx >> 2, cc = idx & 3;
            cp_async_16(vb + (uint32_t)(d * 80 + cc * 16),
                &vT[((size_t)(b * KVH + gkv) * DD + d) * SS + kt0 + cc * 8]);
        }
        CP_COMMIT();
    };

    float o[16][4];
    #pragma unroll
    for (int dt = 0; dt < 16; dt++)
        #pragma unroll
        for (int i = 0; i < 4; i++) o[dt][i] = 0.f;
    float m_a = -1e30f, m_b = -1e30f, l_a = 0.f, l_b = 0.f;

    const int i_lo = q0 + warp * 16;
    const int i_a  = i_lo + g;
    const int i_b  = i_a + 8;

    issue_tile(0);

    for (int t = 0; t < ntile; t++) {
        CP_WAIT(0);
        __syncthreads();
        if (t + 1 < ntile) issue_tile(t + 1);

        const int kt0 = js + t * KTA;
        const uint32_t kb = smb + (t & 1 ? OFF_K1 : OFF_K0);
        const uint32_t vb = smb + (t & 1 ? OFF_V1 : OFF_V0);

        // ---- S = Q K^T : 8 k16 steps over d ----
        float s[4][4];
        #pragma unroll
        for (int nt = 0; nt < 4; nt++)
            #pragma unroll
            for (int i = 0; i < 4; i++) s[nt][i] = 0.f;

        #pragma unroll
        for (int kk = 0; kk < 8; kk++) {
            const uint32_t rowb = kb + (uint32_t)(kk >> 2) * (32 * 128);
            const uint32_t offK = ((uint32_t)(kk & 3) * 32 + colK) ^ xr;
            uint32_t bf[4][2];
            #pragma unroll
            for (int p = 0; p < 2; p++) {
                uint32_t bq[4];
                ldsm4(bq, rowb + relK[p] + offK);
                bf[2*p][0] = bq[0]; bf[2*p][1] = bq[1];
                bf[2*p+1][0] = bq[2]; bf[2*p+1][1] = bq[3];
            }
            #pragma unroll
            for (int nt = 0; nt < 4; nt++)
                mma_f16(s[nt], qf[kk], bf[nt]);
        }

        // ---- mask ----
        #pragma unroll
        for (int nt = 0; nt < 4; nt++) {
            const int j0 = kt0 + nt * 8;
            const bool allvalid = (j0 + 7 <= i_lo) && (i_lo + 15 - j0 < WINW);
            if (!allvalid) {
                const int ja = j0 + 2 * l4, jb = ja + 1;
                if (!(ja <= i_a && i_a - ja < WINW)) s[nt][0] = MASKVAL;
                if (!(jb <= i_a && i_a - jb < WINW)) s[nt][1] = MASKVAL;
                if (!(ja <= i_b && i_b - ja < WINW)) s[nt][2] = MASKVAL;
                if (!(jb <= i_b && i_b - jb < WINW)) s[nt][3] = MASKVAL;
            }
        }

        // ---- online softmax ----
        float ta = MASKVAL, tb = MASKVAL;
        #pragma unroll
        for (int nt = 0; nt < 4; nt++) {
            ta = fmaxf(ta, fmaxf(s[nt][0], s[nt][1]));
            tb = fmaxf(tb, fmaxf(s[nt][2], s[nt][3]));
        }
        ta = fmaxf(ta, __shfl_xor_sync(0xffffffffu, ta, 1));
        ta = fmaxf(ta, __shfl_xor_sync(0xffffffffu, ta, 2));
        tb = fmaxf(tb, __shfl_xor_sync(0xffffffffu, tb, 1));
        tb = fmaxf(tb, __shfl_xor_sync(0xffffffffu, tb, 2));

        const float mna = fmaxf(m_a, ta);
        const float mnb = fmaxf(m_b, tb);
        const float alpha_a = __expf(m_a - mna);
        const float alpha_b = __expf(m_b - mnb);
        m_a = mna; m_b = mnb;

        float ra = 0.f, rb = 0.f;
        #pragma unroll
        for (int nt = 0; nt < 4; nt++) {
            s[nt][0] = __expf(s[nt][0] - m_a);
            s[nt][1] = __expf(s[nt][1] - m_a);
            s[nt][2] = __expf(s[nt][2] - m_b);
            s[nt][3] = __expf(s[nt][3] - m_b);
            ra += s[nt][0] + s[nt][1];
            rb += s[nt][2] + s[nt][3];
        }
        ra += __shfl_xor_sync(0xffffffffu, ra, 1);
        ra += __shfl_xor_sync(0xffffffffu, ra, 2);
        rb += __shfl_xor_sync(0xffffffffu, rb, 1);
        rb += __shfl_xor_sync(0xffffffffu, rb, 2);
        l_a = l_a * alpha_a + ra;
        l_b = l_b * alpha_b + rb;

        #pragma unroll
        for (int dt = 0; dt < 16; dt++) {
            o[dt][0] *= alpha_a; o[dt][1] *= alpha_a;
            o[dt][2] *= alpha_b; o[dt][3] *= alpha_b;
        }

        // ---- O += P V : fp16 A-frag == C-frag rows, no shuffles ----
        #pragma unroll
        for (int kk = 0; kk < 2; kk++) {       // 2 x k16 over 32 keys
            uint32_t ap[4];
            ap[0] = pack2h(s[2*kk][0],   s[2*kk][1]);
            ap[1] = pack2h(s[2*kk][2],   s[2*kk][3]);
            ap[2] = pack2h(s[2*kk+1][0], s[2*kk+1][1]);
            ap[3] = pack2h(s[2*kk+1][2], s[2*kk+1][3]);
            #pragma unroll
            for (int dtp = 0; dtp < 8; dtp++) {
                uint32_t addr = vb + (uint32_t)(dtp * 16 + r + (qq >> 1) * 8) * 80
                                   + (uint32_t)kk * 32 + (uint32_t)(qq & 1) * 16;
                uint32_t bq[4];
                ldsm4(bq, addr);
                uint32_t b0[2] = { bq[0], bq[1] };
                uint32_t b1[2] = { bq[2], bq[3] };
                mma_f16(o[2*dtp],     ap, b0);
                mma_f16(o[2*dtp + 1], ap, b1);
            }
        }
    }

    const float inv_a = 1.0f / l_a;
    const float inv_b = 1.0f / l_b;
    #pragma unroll
    for (int dt = 0; dt < 16; dt++) {
        const int col = h * DD + dt * 8 + 2 * l4;
        *(uint32_t*)&out[(size_t)(b * SS + i_a) * (HH * DD) + col] =
            pack2h(o[dt][0] * inv_a, o[dt][1] * inv_a);
        *(uint32_t*)&out[(size_t)(b * SS + i_b) * (HH * DD) + col] =
            pack2h(o[dt][2] * inv_b, o[dt][3] * inv_b);
    }
}

// ---------------------------------------------------------------------------
extern "C" void kernel_launch(void* const* d_in, const int* in_sizes, int n_in,
                              void* d_out, int out_size)
{
    const float* x     = (const float*)d_in[0];
    const float* w_qkv = (const float*)d_in[1];
    const float* w_o   = (const float*)d_in[2];
    float* out = (float*)d_out;

    float*  qkv_ptr = nullptr;
    __half* attn_h  = nullptr;
    __half* xh      = nullptr;
    __half* wqkvTh  = nullptr;
    __half* woTh    = nullptr;
    __half* q16p    = nullptr;
    __half* k16p    = nullptr;
    __half* vTp     = nullptr;
    cudaGetSymbolAddress((void**)&qkv_ptr, g_qkv);
    cudaGetSymbolAddress((void**)&attn_h,  g_attn_h);
    cudaGetSymbolAddress((void**)&xh,      g_xh);
    cudaGetSymbolAddress((void**)&wqkvTh,  g_wqkvT_h);
    cudaGetSymbolAddress((void**)&woTh,    g_woT_h);
    cudaGetSymbolAddress((void**)&q16p,    g_q16);
    cudaGetSymbolAddress((void**)&k16p,    g_k16);
    cudaGetSymbolAddress((void**)&vTp,     g_vT);

    cudaFuncSetAttribute(gemm_f16_v6,
                         cudaFuncAttributeMaxDynamicSharedMemorySize, GEMM_SMEM);
    cudaFuncSetAttribute(attn_f16_v4,
                         cudaFuncAttributeMaxDynamicSharedMemorySize, ATT_SMEM);

    // 0) prep: x -> half; weights -> transposed half [N][K]
    {
        int n4 = (NROWS * EE) / 4;
        cvt_half_kernel<<<(n4 + 255) / 256, 256>>>(x, xh, n4);
        dim3 blk(32, 8);
        transpose_cvt_h_kernel<<<dim3(QKVW / 32, EE / 32), blk>>>(w_qkv, wqkvTh, EE, QKVW);
        transpose_cvt_h_kernel<<<dim3(EE / 32, EE / 32), blk>>>(w_o, woTh, EE, EE);
    }
    // 1) QKV projection (fp16 tensor)
    {
        dim3 grid(QKVW / 128, NROWS / 256);
        gemm_f16_v6<<<grid, 256, GEMM_SMEM>>>(xh, wqkvTh, qkv_ptr, NROWS, QKVW, EE);
    }
    // 2) RoPE -> q16/k16; V transpose -> vT
    {
        rope_cvt_kernel<<<NROWS, 256>>>(qkv_ptr, q16p, k16p);
        dim3 blk(32, 8);
        vtrans_kernel<<<dim3((KVH * DD) / 32, SS / 32, BB), blk>>>(qkv_ptr, vTp);
    }
    // 3) Flash attention (fp16)
    {
        dim3 grid(SS / BQA, HH, BB);
        attn_f16_v4<<<grid, 128, ATT_SMEM>>>(q16p, k16p, vTp, attn_h);
    }
    // 4) Output projection (fp16 tensor)
    {
        dim3 grid(EE / 128, NROWS / 256);
        gemm_f16_v6<<<grid, 256, GEMM_SMEM>>>(attn_h, woTh, out, NROWS, EE, EE);
    }
}